// round 1
// baseline (speedup 1.0000x reference)
#include <cuda_runtime.h>
#include <cuda_bf16.h>
#include <math.h>

// ---------------------------------------------------------------------------
// CircleLoss fused pipeline:
//   1) conv_labels : detect int64 vs int32 labels, convert to int32 scratch
//   2) gemm_sim    : sim = E * E^T  (fp32 SIMT tiled GEMM, symmetric: only
//                    upper-triangular blocks computed, mirrored on store)
//   3) epilogue    : per-row pos_min/neg_max + 4 online masked logsumexps,
//                    per-row loss + low/med/high flags
//   4) final_reduce: deterministic tree reduction -> out[0..3]
// ---------------------------------------------------------------------------

#define MAXB 4096
#define MAXBB ((size_t)MAXB * (size_t)MAXB)

__device__ float g_sim[MAXBB];          // 64 MB similarity matrix
__device__ float g_rowout[4 * MAXB];    // per-row [loss | low | med | high]
__device__ int   g_lab[MAXB];

#define SCALE_C   32.0f
#define MARGIN_P  0.75f
#define MARGIN_N  0.25f
#define OPT_P     1.25f
#define OPT_N     (-0.25f)
#define THETA_C   0.25f
#define NEG_INF   (-INFINITY)

// ------------------------------- labels -----------------------------------
__global__ void conv_labels(const void* __restrict__ lab, int B) {
    __shared__ int is64;
    if (threadIdx.x == 0) {
        // If the buffer really is int64, every value is a class id in [0, B).
        // If it is int32, the int64 view combines two random labels; the high
        // word is almost surely nonzero somewhere in the first 64 entries.
        const long long* p = (const long long*)lab;
        int ok = 1;
        int n = B < 64 ? B : 64;
        for (int i = 0; i < n; i++) {
            long long v = p[i];
            if (v < 0 || v >= (long long)B) { ok = 0; break; }
        }
        is64 = ok;
    }
    __syncthreads();
    if (is64) {
        const long long* p = (const long long*)lab;
        for (int i = threadIdx.x; i < B; i += blockDim.x) g_lab[i] = (int)p[i];
    } else {
        const int* p = (const int*)lab;
        for (int i = threadIdx.x; i < B; i += blockDim.x) g_lab[i] = p[i];
    }
}

// ------------------------------- GEMM --------------------------------------
// C = E * E^T, 64x64 block tile, BK=32, 256 threads, 4x4 per-thread microtile.
// Only blocks with bx >= by are computed; result mirrored into both halves.
__global__ __launch_bounds__(256) void gemm_sim(const float* __restrict__ E,
                                                int B, int D) {
    const int bx = blockIdx.x, by = blockIdx.y;
    if (bx < by) return;

    __shared__ float As[64][36];   // [m][k], padded (144B rows, 16B aligned)
    __shared__ float Bs[32][68];   // [k][n], padded (272B rows, 16B aligned)

    const int tid = threadIdx.x;
    const int tx = tid & 15;       // 0..15 -> 4 cols each
    const int ty = tid >> 4;       // 0..15 -> 4 rows each
    const int rowBase = by * 64;
    const int colBase = bx * 64;

    float acc[4][4];
#pragma unroll
    for (int i = 0; i < 4; i++)
#pragma unroll
        for (int j = 0; j < 4; j++) acc[i][j] = 0.0f;

    for (int k0 = 0; k0 < D; k0 += 32) {
        // Load 64x32 tiles of A-rows and B-rows. 512 float4 each, 2/thread.
#pragma unroll
        for (int t = 0; t < 2; t++) {
            int ff = tid + t * 256;        // 0..511
            int r  = ff >> 3;              // 0..63
            int kc = (ff & 7) << 2;        // 0,4,...,28
            float4 va = *(const float4*)&E[(size_t)(rowBase + r) * D + k0 + kc];
            *(float4*)&As[r][kc] = va;
            float4 vb = *(const float4*)&E[(size_t)(colBase + r) * D + k0 + kc];
            Bs[kc + 0][r] = vb.x;
            Bs[kc + 1][r] = vb.y;
            Bs[kc + 2][r] = vb.z;
            Bs[kc + 3][r] = vb.w;
        }
        __syncthreads();

#pragma unroll
        for (int k = 0; k < 32; k++) {
            float4 bv = *(const float4*)&Bs[k][tx * 4];
            float a0 = As[ty * 4 + 0][k];
            float a1 = As[ty * 4 + 1][k];
            float a2 = As[ty * 4 + 2][k];
            float a3 = As[ty * 4 + 3][k];
            acc[0][0] += a0 * bv.x; acc[0][1] += a0 * bv.y;
            acc[0][2] += a0 * bv.z; acc[0][3] += a0 * bv.w;
            acc[1][0] += a1 * bv.x; acc[1][1] += a1 * bv.y;
            acc[1][2] += a1 * bv.z; acc[1][3] += a1 * bv.w;
            acc[2][0] += a2 * bv.x; acc[2][1] += a2 * bv.y;
            acc[2][2] += a2 * bv.z; acc[2][3] += a2 * bv.w;
            acc[3][0] += a3 * bv.x; acc[3][1] += a3 * bv.y;
            acc[3][2] += a3 * bv.z; acc[3][3] += a3 * bv.w;
        }
        __syncthreads();
    }

    // Store block (and its mirror, when off-diagonal).
#pragma unroll
    for (int i = 0; i < 4; i++) {
        int r = rowBase + ty * 4 + i;
        float4 v = make_float4(acc[i][0], acc[i][1], acc[i][2], acc[i][3]);
        *(float4*)&g_sim[(size_t)r * B + colBase + tx * 4] = v;
    }
    if (bx != by) {
#pragma unroll
        for (int j = 0; j < 4; j++) {
            int c = colBase + tx * 4 + j;
            float4 v = make_float4(acc[0][j], acc[1][j], acc[2][j], acc[3][j]);
            *(float4*)&g_sim[(size_t)c * B + rowBase + ty * 4] = v;
        }
    }
}

// --------------------------- online LSE helpers ----------------------------
__device__ __forceinline__ void lse_add(float& m, float& s, float v) {
    if (v > m) {                       // also handles m == -inf (expf(-inf)=0)
        s = s * expf(m - v) + 1.0f;
        m = v;
    } else {
        s += expf(v - m);
    }
}

__device__ __forceinline__ void lse_merge(float& m1, float& s1, float m2, float s2) {
    if (m2 == NEG_INF) return;         // empty contribution
    if (m2 > m1) {
        s1 = s1 * expf(m1 - m2) + s2;  // m1 may be -inf -> s1 term vanishes
        m1 = m2;
    } else {
        s1 += s2 * expf(m2 - m1);
    }
}

// ------------------------------- epilogue ----------------------------------
__global__ __launch_bounds__(128) void epilogue(int B) {
    const int row = blockIdx.x;
    const float* __restrict__ srow = g_sim + (size_t)row * B;
    const int li = g_lab[row];
    const int tid = threadIdx.x;

    float pmin = INFINITY, nmax = NEG_INF;
    float m1 = NEG_INF, s1 = 0.f;   // pos & (s + theta < margin_p)
    float m2 = NEG_INF, s2 = 0.f;   // pos & (s < margin_p)
    float m3 = NEG_INF, s3 = 0.f;   // neg & (s - theta > margin_n)
    float m4 = NEG_INF, s4 = 0.f;   // neg & (s > margin_n)

    for (int j = tid; j < B; j += blockDim.x) {
        float s = srow[j];
        bool same = (g_lab[j] == li);
        if (same) {
            pmin = fminf(pmin, s);
            float ip = -SCALE_C * fmaxf(OPT_P - s, 0.0f) * (s - MARGIN_P);
            if (s + THETA_C < MARGIN_P) lse_add(m1, s1, ip);
            if (s < MARGIN_P)           lse_add(m2, s2, ip);
        } else {
            nmax = fmaxf(nmax, s);
            float in_ = SCALE_C * fmaxf(s - OPT_N, 0.0f) * (s - MARGIN_N);
            if (s - THETA_C > MARGIN_N) lse_add(m3, s3, in_);
            if (s > MARGIN_N)           lse_add(m4, s4, in_);
        }
    }

    // warp reduce
#pragma unroll
    for (int off = 16; off > 0; off >>= 1) {
        pmin = fminf(pmin, __shfl_down_sync(0xffffffffu, pmin, off));
        nmax = fmaxf(nmax, __shfl_down_sync(0xffffffffu, nmax, off));
        float mm, ss;
        mm = __shfl_down_sync(0xffffffffu, m1, off);
        ss = __shfl_down_sync(0xffffffffu, s1, off);
        lse_merge(m1, s1, mm, ss);
        mm = __shfl_down_sync(0xffffffffu, m2, off);
        ss = __shfl_down_sync(0xffffffffu, s2, off);
        lse_merge(m2, s2, mm, ss);
        mm = __shfl_down_sync(0xffffffffu, m3, off);
        ss = __shfl_down_sync(0xffffffffu, s3, off);
        lse_merge(m3, s3, mm, ss);
        mm = __shfl_down_sync(0xffffffffu, m4, off);
        ss = __shfl_down_sync(0xffffffffu, s4, off);
        lse_merge(m4, s4, mm, ss);
    }

    __shared__ float red[4][10];
    const int wid = tid >> 5, lane = tid & 31;
    if (lane == 0) {
        red[wid][0] = pmin; red[wid][1] = nmax;
        red[wid][2] = m1;   red[wid][3] = s1;
        red[wid][4] = m2;   red[wid][5] = s2;
        red[wid][6] = m3;   red[wid][7] = s3;
        red[wid][8] = m4;   red[wid][9] = s4;
    }
    __syncthreads();

    if (tid == 0) {
        for (int w = 1; w < 4; w++) {
            pmin = fminf(pmin, red[w][0]);
            nmax = fmaxf(nmax, red[w][1]);
            lse_merge(m1, s1, red[w][2], red[w][3]);
            lse_merge(m2, s2, red[w][4], red[w][5]);
            lse_merge(m3, s3, red[w][6], red[w][7]);
            lse_merge(m4, s4, red[w][8], red[w][9]);
        }

        float se_pos;
        if (m1 > NEG_INF)      se_pos = m1 + logf(s1);
        else if (m2 > NEG_INF) se_pos = m2 + logf(s2);
        else                   se_pos = -SCALE_C * fmaxf(OPT_P - pmin, 0.0f) * (pmin - MARGIN_P);

        float se_neg;
        if (m3 > NEG_INF)      se_neg = m3 + logf(s3);
        else if (m4 > NEG_INF) se_neg = m4 + logf(s4);
        else if (nmax > NEG_INF)
                               se_neg = SCALE_C * fmaxf(nmax - OPT_N, 0.0f) * (nmax - MARGIN_N);
        else                   se_neg = 0.0f;   // unreachable for this data

        float z = se_pos + se_neg;
        float pl = (z > 0.0f) ? (z + log1pf(expf(-z))) : log1pf(expf(z));

        float lowf  = (pmin > nmax) ? 1.0f : 0.0f;
        float medf  = (lowf != 0.0f && pmin > MARGIN_P) ? 1.0f : 0.0f;
        float highf = (medf != 0.0f && nmax < MARGIN_N) ? 1.0f : 0.0f;

        g_rowout[0 * B + row] = pl;
        g_rowout[1 * B + row] = lowf;
        g_rowout[2 * B + row] = medf;
        g_rowout[3 * B + row] = highf;
    }
}

// ------------------------------ final reduce -------------------------------
__global__ __launch_bounds__(256) void final_reduce(float* __restrict__ out, int B) {
    __shared__ float sh[256];
    const int tid = threadIdx.x;
    for (int c = 0; c < 4; c++) {
        float acc = 0.0f;
        for (int i = tid; i < B; i += 256) acc += g_rowout[c * B + i];
        sh[tid] = acc;
        __syncthreads();
        for (int off = 128; off > 0; off >>= 1) {
            if (tid < off) sh[tid] += sh[tid + off];
            __syncthreads();
        }
        if (tid == 0) out[c] = sh[0] / (float)B;
        __syncthreads();
    }
}

// ------------------------------- launch ------------------------------------
extern "C" void kernel_launch(void* const* d_in, const int* in_sizes, int n_in,
                              void* d_out, int out_size) {
    const float* emb = (const float*)d_in[0];
    const void*  lab = d_in[1];
    const int B = in_sizes[1];
    const int D = in_sizes[0] / B;

    conv_labels<<<1, 256>>>(lab, B);

    dim3 grid(B / 64, B / 64);
    gemm_sim<<<grid, 256>>>(emb, B, D);

    epilogue<<<B, 128>>>(B);

    final_reduce<<<1, 256>>>((float*)d_out, B);
}

// round 3
// speedup vs baseline: 2.5218x; 2.5218x over previous
#include <cuda_runtime.h>
#include <cuda.h>
#include <cuda_bf16.h>
#include <math.h>
#include <stdint.h>

// ---------------------------------------------------------------------------
// CircleLoss, tf32 mma.sync edition (sm_100 baseline target — no tcgen05):
//   1) conv_labels : int64/int32 detect -> g_lab
//   2) to_tf32     : E fp32 -> tf32 (rna) scratch
//   3) gemm_mma    : sim = E E^T via mma.sync m16n8k8 tf32, cp.async double
//                    buffer, 128x128 tile, symmetric blocks + mirror store
//   4) epilogue    : per-row pos_min/neg_max + 4 online masked LSEs
//   5) final_reduce: deterministic tree reduction -> out[0..3]
// ---------------------------------------------------------------------------

#define MAXB 4096
#define MAXD 512
#define MAXBB ((size_t)MAXB * (size_t)MAXB)

__device__ float g_sim[MAXBB];            // 64 MB
__device__ float g_etf[MAXB * MAXD];      // 8 MB tf32-converted embeddings
__device__ float g_rowout[4 * MAXB];
__device__ int   g_lab[MAXB];

#define SCALE_C   32.0f
#define MARGIN_P  0.75f
#define MARGIN_N  0.25f
#define OPT_P     1.25f
#define OPT_N     (-0.25f)
#define THETA_C   0.25f
#define NEG_INF   (-INFINITY)

// ------------------------------ helpers ------------------------------------
__device__ __forceinline__ uint32_t smem_u32(const void* p) {
    uint32_t a;
    asm("{ .reg .u64 t; cvta.to.shared.u64 t, %1; cvt.u32.u64 %0, t; }"
        : "=r"(a) : "l"(p));
    return a;
}
__device__ __forceinline__ void cp_async16(uint32_t dst, const void* src) {
    asm volatile("cp.async.cg.shared.global [%0], [%1], 16;" :: "r"(dst), "l"(src));
}
__device__ __forceinline__ void mma_tf32_frag(float* d, const uint32_t* a, const uint32_t* b) {
    asm volatile(
        "mma.sync.aligned.m16n8k8.row.col.f32.tf32.tf32.f32 "
        "{%0,%1,%2,%3}, {%4,%5,%6,%7}, {%8,%9}, {%0,%1,%2,%3};"
        : "+f"(d[0]), "+f"(d[1]), "+f"(d[2]), "+f"(d[3])
        : "r"(a[0]), "r"(a[1]), "r"(a[2]), "r"(a[3]), "r"(b[0]), "r"(b[1]));
}

// ------------------------------- labels ------------------------------------
__global__ void conv_labels(const void* __restrict__ lab, int B) {
    __shared__ int is64;
    if (threadIdx.x == 0) {
        const long long* p = (const long long*)lab;
        int ok = 1;
        int n = B < 64 ? B : 64;
        for (int i = 0; i < n; i++) {
            long long v = p[i];
            if (v < 0 || v >= (long long)B) { ok = 0; break; }
        }
        is64 = ok;
    }
    __syncthreads();
    if (is64) {
        const long long* p = (const long long*)lab;
        for (int i = threadIdx.x; i < B; i += blockDim.x) g_lab[i] = (int)p[i];
    } else {
        const int* p = (const int*)lab;
        for (int i = threadIdx.x; i < B; i += blockDim.x) g_lab[i] = p[i];
    }
}

// --------------------------- tf32 conversion -------------------------------
__global__ __launch_bounds__(256) void to_tf32(const float* __restrict__ e, int n) {
    int i = blockIdx.x * 256 + threadIdx.x;
    if (i < n) {
        uint32_t o;
        asm("cvt.rna.tf32.f32 %0, %1;" : "=r"(o) : "f"(e[i]));
        ((uint32_t*)g_etf)[i] = o;
    }
}

// --------------------------- tensor-core GEMM ------------------------------
// 128x128 tile, BK=32, 256 threads = 8 warps (4 m x 2 n), warp tile 32x64.
// smem: per stage A[128][36] + B[128][36] floats; 2 stages.
#define BK 32
#define ROWP 36                              // padded row pitch (floats)
#define STG_FLT (2 * 128 * ROWP)             // 9216 floats / stage
#define SMEM_GEMM (2 * STG_FLT * 4)          // 73728 bytes

__global__ __launch_bounds__(256, 2) void gemm_mma(int B, int D) {
    const int bx = blockIdx.x, by = blockIdx.y;
    if (bx < by) return;

    extern __shared__ float sm[];
    const uint32_t smb = smem_u32(sm);
    const int tid  = threadIdx.x;
    const int warp = tid >> 5, lane = tid & 31;
    const int wm = warp & 3, wn = warp >> 2;       // 4 x 2 warp grid
    const int fr = lane >> 2, fq = lane & 3;       // fragment row / quad col

    const float* gA = g_etf + (size_t)(by * 128) * D;
    const float* gB = g_etf + (size_t)(bx * 128) * D;

    float acc[2][8][4];
#pragma unroll
    for (int mt = 0; mt < 2; mt++)
#pragma unroll
        for (int nt = 0; nt < 8; nt++)
#pragma unroll
            for (int e = 0; e < 4; e++) acc[mt][nt][e] = 0.0f;

    const int nK = D / BK;                         // 16

    // stage loader: 128 rows x 32 floats for A and B, 8 float4/row
#define LOAD_STAGE(s, k0)                                                      \
    do {                                                                       \
        uint32_t ab = smb + (uint32_t)(s) * (STG_FLT * 4);                     \
        uint32_t bb = ab + 128 * ROWP * 4;                                     \
        _Pragma("unroll")                                                      \
        for (int i = 0; i < 4; i++) {                                          \
            int c = tid + 256 * i;                                             \
            int r = c >> 3;                                                    \
            int kc = (c & 7) << 2;                                             \
            cp_async16(ab + (uint32_t)(r * ROWP + kc) * 4,                     \
                       gA + (size_t)r * D + (k0) + kc);                        \
            cp_async16(bb + (uint32_t)(r * ROWP + kc) * 4,                     \
                       gB + (size_t)r * D + (k0) + kc);                        \
        }                                                                      \
        asm volatile("cp.async.commit_group;" ::: "memory");                   \
    } while (0)

    LOAD_STAGE(0, 0);

    for (int t = 0; t < nK; t++) {
        if (t + 1 < nK) {
            LOAD_STAGE((t + 1) & 1, (t + 1) * BK);
            asm volatile("cp.async.wait_group 1;" ::: "memory");
        } else {
            asm volatile("cp.async.wait_group 0;" ::: "memory");
        }
        __syncthreads();

        const float* As = sm + (t & 1) * STG_FLT;
        const float* Bs = As + 128 * ROWP;

#pragma unroll
        for (int ks = 0; ks < 4; ks++) {
            const int k = ks * 8;
            uint32_t a[2][4], b[8][2];
#pragma unroll
            for (int mt = 0; mt < 2; mt++) {
                const int r0 = wm * 32 + mt * 16 + fr;
                a[mt][0] = __float_as_uint(As[r0 * ROWP + k + fq]);
                a[mt][1] = __float_as_uint(As[(r0 + 8) * ROWP + k + fq]);
                a[mt][2] = __float_as_uint(As[r0 * ROWP + k + fq + 4]);
                a[mt][3] = __float_as_uint(As[(r0 + 8) * ROWP + k + fq + 4]);
            }
#pragma unroll
            for (int nt = 0; nt < 8; nt++) {
                const int c0 = wn * 64 + nt * 8 + fr;
                b[nt][0] = __float_as_uint(Bs[c0 * ROWP + k + fq]);
                b[nt][1] = __float_as_uint(Bs[c0 * ROWP + k + fq + 4]);
            }
#pragma unroll
            for (int mt = 0; mt < 2; mt++)
#pragma unroll
                for (int nt = 0; nt < 8; nt++)
                    mma_tf32_frag(acc[mt][nt], a[mt], b[nt]);
        }
        __syncthreads();
    }

    // store block + mirror
    const int gr = by * 128 + wm * 32;
    const int gc = bx * 128 + wn * 64;
#pragma unroll
    for (int mt = 0; mt < 2; mt++) {
#pragma unroll
        for (int nt = 0; nt < 8; nt++) {
            const int r0 = gr + mt * 16 + fr;
            const int c0 = gc + nt * 8 + 2 * fq;
            *(float2*)&g_sim[(size_t)r0 * B + c0] =
                make_float2(acc[mt][nt][0], acc[mt][nt][1]);
            *(float2*)&g_sim[(size_t)(r0 + 8) * B + c0] =
                make_float2(acc[mt][nt][2], acc[mt][nt][3]);
            if (bx != by) {
                g_sim[(size_t)c0 * B + r0]           = acc[mt][nt][0];
                g_sim[(size_t)(c0 + 1) * B + r0]     = acc[mt][nt][1];
                g_sim[(size_t)c0 * B + r0 + 8]       = acc[mt][nt][2];
                g_sim[(size_t)(c0 + 1) * B + r0 + 8] = acc[mt][nt][3];
            }
        }
    }
}

// --------------------------- online LSE helpers ----------------------------
__device__ __forceinline__ void lse_add(float& m, float& s, float v) {
    if (v > m) { s = s * expf(m - v) + 1.0f; m = v; }
    else       { s += expf(v - m); }
}
__device__ __forceinline__ void lse_merge(float& m1, float& s1, float m2, float s2) {
    if (m2 == NEG_INF) return;
    if (m2 > m1) { s1 = s1 * expf(m1 - m2) + s2; m1 = m2; }
    else         { s1 += s2 * expf(m2 - m1); }
}

// ------------------------------- epilogue ----------------------------------
__global__ __launch_bounds__(128) void epilogue(int B) {
    __shared__ int slab[MAXB];
    const int tid = threadIdx.x;
    for (int i = tid; i < B; i += 128) slab[i] = g_lab[i];
    __syncthreads();

    const int row = blockIdx.x;
    const float4* __restrict__ srow = (const float4*)(g_sim + (size_t)row * B);
    const int li = slab[row];

    float pmin = INFINITY, nmax = NEG_INF;
    float m1 = NEG_INF, s1 = 0.f, m2 = NEG_INF, s2 = 0.f;
    float m3 = NEG_INF, s3 = 0.f, m4 = NEG_INF, s4 = 0.f;

    for (int j4 = tid; j4 < B / 4; j4 += 128) {
        float4 v = srow[j4];
        const int jb = j4 * 4;
#pragma unroll
        for (int q = 0; q < 4; q++) {
            float s = (q == 0) ? v.x : (q == 1) ? v.y : (q == 2) ? v.z : v.w;
            if (slab[jb + q] == li) {
                pmin = fminf(pmin, s);
                float ip = -SCALE_C * fmaxf(OPT_P - s, 0.0f) * (s - MARGIN_P);
                if (s + THETA_C < MARGIN_P) lse_add(m1, s1, ip);
                if (s < MARGIN_P)           lse_add(m2, s2, ip);
            } else {
                nmax = fmaxf(nmax, s);
                if (s > MARGIN_N) {
                    float in_ = SCALE_C * fmaxf(s - OPT_N, 0.0f) * (s - MARGIN_N);
                    if (s - THETA_C > MARGIN_N) lse_add(m3, s3, in_);
                    lse_add(m4, s4, in_);
                }
            }
        }
    }

#pragma unroll
    for (int off = 16; off > 0; off >>= 1) {
        pmin = fminf(pmin, __shfl_down_sync(0xffffffffu, pmin, off));
        nmax = fmaxf(nmax, __shfl_down_sync(0xffffffffu, nmax, off));
        float mm, ss;
        mm = __shfl_down_sync(0xffffffffu, m1, off); ss = __shfl_down_sync(0xffffffffu, s1, off);
        lse_merge(m1, s1, mm, ss);
        mm = __shfl_down_sync(0xffffffffu, m2, off); ss = __shfl_down_sync(0xffffffffu, s2, off);
        lse_merge(m2, s2, mm, ss);
        mm = __shfl_down_sync(0xffffffffu, m3, off); ss = __shfl_down_sync(0xffffffffu, s3, off);
        lse_merge(m3, s3, mm, ss);
        mm = __shfl_down_sync(0xffffffffu, m4, off); ss = __shfl_down_sync(0xffffffffu, s4, off);
        lse_merge(m4, s4, mm, ss);
    }

    __shared__ float red[4][10];
    const int wid = tid >> 5, lane = tid & 31;
    if (lane == 0) {
        red[wid][0] = pmin; red[wid][1] = nmax;
        red[wid][2] = m1; red[wid][3] = s1; red[wid][4] = m2; red[wid][5] = s2;
        red[wid][6] = m3; red[wid][7] = s3; red[wid][8] = m4; red[wid][9] = s4;
    }
    __syncthreads();

    if (tid == 0) {
        for (int w = 1; w < 4; w++) {
            pmin = fminf(pmin, red[w][0]);
            nmax = fmaxf(nmax, red[w][1]);
            lse_merge(m1, s1, red[w][2], red[w][3]);
            lse_merge(m2, s2, red[w][4], red[w][5]);
            lse_merge(m3, s3, red[w][6], red[w][7]);
            lse_merge(m4, s4, red[w][8], red[w][9]);
        }
        float se_pos;
        if (m1 > NEG_INF)      se_pos = m1 + logf(s1);
        else if (m2 > NEG_INF) se_pos = m2 + logf(s2);
        else                   se_pos = -SCALE_C * fmaxf(OPT_P - pmin, 0.0f) * (pmin - MARGIN_P);
        float se_neg;
        if (m3 > NEG_INF)      se_neg = m3 + logf(s3);
        else if (m4 > NEG_INF) se_neg = m4 + logf(s4);
        else if (nmax > NEG_INF)
                               se_neg = SCALE_C * fmaxf(nmax - OPT_N, 0.0f) * (nmax - MARGIN_N);
        else                   se_neg = 0.0f;

        float z = se_pos + se_neg;
        float pl = (z > 0.0f) ? (z + log1pf(expf(-z))) : log1pf(expf(z));
        float lowf  = (pmin > nmax) ? 1.0f : 0.0f;
        float medf  = (lowf != 0.0f && pmin > MARGIN_P) ? 1.0f : 0.0f;
        float highf = (medf != 0.0f && nmax < MARGIN_N) ? 1.0f : 0.0f;

        g_rowout[0 * B + row] = pl;
        g_rowout[1 * B + row] = lowf;
        g_rowout[2 * B + row] = medf;
        g_rowout[3 * B + row] = highf;
    }
}

// ------------------------------ final reduce -------------------------------
__global__ __launch_bounds__(1024) void final_reduce(float* __restrict__ out, int B) {
    __shared__ float4 sh[1024];
    const int tid = threadIdx.x;
    float a0 = 0, a1 = 0, a2 = 0, a3 = 0;
    for (int i = tid; i < B; i += 1024) {
        a0 += g_rowout[i];
        a1 += g_rowout[B + i];
        a2 += g_rowout[2 * B + i];
        a3 += g_rowout[3 * B + i];
    }
    sh[tid] = make_float4(a0, a1, a2, a3);
    __syncthreads();
    for (int off = 512; off > 0; off >>= 1) {
        if (tid < off) {
            float4 a = sh[tid], b = sh[tid + off];
            sh[tid] = make_float4(a.x + b.x, a.y + b.y, a.z + b.z, a.w + b.w);
        }
        __syncthreads();
    }
    if (tid == 0) {
        float inv = 1.0f / (float)B;
        out[0] = sh[0].x * inv;
        out[1] = sh[0].y * inv;
        out[2] = sh[0].z * inv;
        out[3] = sh[0].w * inv;
    }
}

// ------------------------------- launch ------------------------------------
extern "C" void kernel_launch(void* const* d_in, const int* in_sizes, int n_in,
                              void* d_out, int out_size) {
    const float* emb = (const float*)d_in[0];
    const void*  lab = d_in[1];
    const int B = in_sizes[1];
    const int D = in_sizes[0] / B;

    cudaFuncSetAttribute(gemm_mma, cudaFuncAttributeMaxDynamicSharedMemorySize, SMEM_GEMM);

    conv_labels<<<1, 256>>>(lab, B);

    const int n = B * D;
    to_tf32<<<(n + 255) / 256, 256>>>(emb, n);

    dim3 grid(B / 128, B / 128);
    gemm_mma<<<grid, 256, SMEM_GEMM>>>(B, D);

    epilogue<<<B, 128>>>(B);

    final_reduce<<<1, 1024>>>((float*)d_out, B);
}

// round 4
// speedup vs baseline: 2.7372x; 1.0854x over previous
#include <cuda_runtime.h>
#include <cuda.h>
#include <cuda_bf16.h>
#include <math.h>
#include <stdint.h>

// ---------------------------------------------------------------------------
// CircleLoss, fused edition:
//   1) sort_labels : int64/int32 detect + deterministic stable counting sort
//                    by class -> g_perm, per-row class ranges g_cs/g_ce
//   2) to_tf32p    : gather-permuted E -> tf32 scratch
//   3) gemm_fused  : sim tile via mma.sync tf32 (128x128, cp.async 2-stage),
//                    tile staged to smem, row-pass + mirror col-pass compute
//                    per-(row, 128col-chunk) partial stats. sim NEVER stored.
//   4) combine     : one warp per row merges 32 partials -> per-row loss/flags
//   5) final_reduce: deterministic tree reduction -> out[0..3]
// ---------------------------------------------------------------------------

#define MAXB 4096
#define MAXD 512

__device__ float g_etf[MAXB * MAXD];           // 8 MB permuted tf32 embeddings
__device__ float g_part[MAXB * 32 * 12];       // 6.3 MB partial states
__device__ float g_rowout[4 * MAXB];
__device__ int   g_perm[MAXB];
__device__ int   g_cs[MAXB];
__device__ int   g_ce[MAXB];

#define SCALE_C   32.0f
#define MARGIN_P  0.75f
#define MARGIN_N  0.25f
#define OPT_P     1.25f
#define OPT_N     (-0.25f)
#define THETA_C   0.25f
#define NEG_INF   (-INFINITY)

// ------------------------------ helpers ------------------------------------
__device__ __forceinline__ uint32_t smem_u32(const void* p) {
    uint32_t a;
    asm("{ .reg .u64 t; cvta.to.shared.u64 t, %1; cvt.u32.u64 %0, t; }"
        : "=r"(a) : "l"(p));
    return a;
}
__device__ __forceinline__ void cp_async16(uint32_t dst, const void* src) {
    asm volatile("cp.async.cg.shared.global [%0], [%1], 16;" :: "r"(dst), "l"(src));
}
__device__ __forceinline__ void mma_tf32_frag(float* d, const uint32_t* a, const uint32_t* b) {
    asm volatile(
        "mma.sync.aligned.m16n8k8.row.col.f32.tf32.tf32.f32 "
        "{%0,%1,%2,%3}, {%4,%5,%6,%7}, {%8,%9}, {%0,%1,%2,%3};"
        : "+f"(d[0]), "+f"(d[1]), "+f"(d[2]), "+f"(d[3])
        : "r"(a[0]), "r"(a[1]), "r"(a[2]), "r"(a[3]), "r"(b[0]), "r"(b[1]));
}
__device__ __forceinline__ void lse_add(float& m, float& s, float v) {
    if (v > m) { s = s * expf(m - v) + 1.0f; m = v; }
    else       { s += expf(v - m); }
}
__device__ __forceinline__ void lse_merge(float& m1, float& s1, float m2, float s2) {
    if (m2 == NEG_INF) return;
    if (m2 > m1) { s1 = s1 * expf(m1 - m2) + s2; m1 = m2; }
    else         { s1 += s2 * expf(m2 - m1); }
}

struct St {
    float pmin, nmax, m1, s1, m2, s2, m3, s3, m4, s4;
    __device__ __forceinline__ void init() {
        pmin = INFINITY; nmax = NEG_INF;
        m1 = m2 = m3 = m4 = NEG_INF; s1 = s2 = s3 = s4 = 0.f;
    }
    __device__ __forceinline__ void upd(float s, int j, int cs, int ce) {
        if (j >= cs && j < ce) {                       // positive (incl. self)
            pmin = fminf(pmin, s);
            if (s < MARGIN_P) {
                float ip = -SCALE_C * fmaxf(OPT_P - s, 0.0f) * (s - MARGIN_P);
                lse_add(m2, s2, ip);
                if (s + THETA_C < MARGIN_P) lse_add(m1, s1, ip);
            }
        } else {
            nmax = fmaxf(nmax, s);
            if (s > MARGIN_N) {
                float in_ = SCALE_C * fmaxf(s - OPT_N, 0.0f) * (s - MARGIN_N);
                lse_add(m4, s4, in_);
                if (s - THETA_C > MARGIN_N) lse_add(m3, s3, in_);
            }
        }
    }
    __device__ __forceinline__ void mergeShfl(int xorMask) {
        const unsigned FM = 0xffffffffu;
        pmin = fminf(pmin, __shfl_xor_sync(FM, pmin, xorMask));
        nmax = fmaxf(nmax, __shfl_xor_sync(FM, nmax, xorMask));
        float mm, ss;
        mm = __shfl_xor_sync(FM, m1, xorMask); ss = __shfl_xor_sync(FM, s1, xorMask);
        lse_merge(m1, s1, mm, ss);
        mm = __shfl_xor_sync(FM, m2, xorMask); ss = __shfl_xor_sync(FM, s2, xorMask);
        lse_merge(m2, s2, mm, ss);
        mm = __shfl_xor_sync(FM, m3, xorMask); ss = __shfl_xor_sync(FM, s3, xorMask);
        lse_merge(m3, s3, mm, ss);
        mm = __shfl_xor_sync(FM, m4, xorMask); ss = __shfl_xor_sync(FM, s4, xorMask);
        lse_merge(m4, s4, mm, ss);
    }
};

// ------------------------- deterministic sort -------------------------------
// Stable counting sort by label. Chunked: thread t owns labels [t*chk, t*chk+chk).
// Per-chunk histograms -> per-class serial chunk prefix -> stable scatter.
#define NC 128
#define SORT_SMEM (MAXB * 4 + 256 * NC * 2 + (NC + 1) * 4 + 64)

__global__ void sort_labels(const void* __restrict__ lab, int B) {
    extern __shared__ char sms[];
    int* slab = (int*)sms;                              // [MAXB]
    unsigned short* hist = (unsigned short*)(sms + MAXB * 4);   // [256][NC]
    int* cstart = (int*)(sms + MAXB * 4 + 256 * NC * 2);        // [NC+1]

    const int t = threadIdx.x;
    const int chk = B / 256;

    __shared__ int is64;
    if (t == 0) {
        const long long* p = (const long long*)lab;
        int ok = 1;
        int n = B < 64 ? B : 64;
        for (int i = 0; i < n; i++) {
            long long v = p[i];
            if (v < 0 || v >= (long long)B) { ok = 0; break; }
        }
        is64 = ok;
    }
    __syncthreads();
    if (is64) {
        const long long* p = (const long long*)lab;
        for (int i = t; i < B; i += 256) slab[i] = (int)p[i];
    } else {
        const int* p = (const int*)lab;
        for (int i = t; i < B; i += 256) slab[i] = p[i];
    }
    for (int i = t; i < 256 * NC; i += 256) hist[i] = 0;
    __syncthreads();

    for (int k = 0; k < chk; k++) hist[t * NC + slab[t * chk + k]]++;
    __syncthreads();

    if (t < NC) {                      // class totals
        int sum = 0;
        for (int ch = 0; ch < 256; ch++) sum += hist[ch * NC + t];
        cstart[t + 1] = sum;
    }
    __syncthreads();
    if (t == 0) {
        cstart[0] = 0;
        for (int c = 1; c <= NC; c++) cstart[c] += cstart[c - 1];
    }
    __syncthreads();
    if (t < NC) {                      // per-class chunk prefix (starts in place)
        int run = cstart[t];
        for (int ch = 0; ch < 256; ch++) {
            int v = hist[ch * NC + t];
            hist[ch * NC + t] = (unsigned short)run;
            run += v;
        }
    }
    __syncthreads();

    for (int k = 0; k < chk; k++) {    // stable scatter
        int i = t * chk + k;
        int c = slab[i];
        int p = hist[t * NC + c]++;
        g_perm[p] = i;
    }
    __syncthreads();

    for (int r = t; r < B; r += 256) { // per-sorted-row class ranges
        int c = slab[g_perm[r]];
        g_cs[r] = cstart[c];
        g_ce[r] = cstart[c + 1];
    }
}

// ------------------- permuted tf32 conversion (gather) ----------------------
__global__ __launch_bounds__(128) void to_tf32p(const float* __restrict__ e, int D) {
    const int r = blockIdx.x;
    const int pr = g_perm[r];
    const float4* src = (const float4*)(e + (size_t)pr * D);
    uint4* dst = (uint4*)(g_etf + (size_t)r * D);
    for (int d = threadIdx.x; d < D / 4; d += 128) {
        float4 v = src[d];
        uint4 o;
        asm("cvt.rna.tf32.f32 %0, %1;" : "=r"(o.x) : "f"(v.x));
        asm("cvt.rna.tf32.f32 %0, %1;" : "=r"(o.y) : "f"(v.y));
        asm("cvt.rna.tf32.f32 %0, %1;" : "=r"(o.z) : "f"(v.z));
        asm("cvt.rna.tf32.f32 %0, %1;" : "=r"(o.w) : "f"(v.w));
        dst[d] = o;
    }
}

// ------------------------ fused GEMM + reduction ----------------------------
#define BK 32
#define ROWP 36
#define STG_FLT (2 * 128 * ROWP)             // floats per stage (A+B)
#define SMEM_GEMM (2 * STG_FLT * 4)          // 73728 bytes
#define TS 136                               // staging tile stride (floats)

__global__ __launch_bounds__(256, 2) void gemm_fused(int B, int D) {
    const int bx = blockIdx.x, by = blockIdx.y;
    if (bx < by) return;

    extern __shared__ float sm[];
    const uint32_t smb = smem_u32(sm);
    const int tid  = threadIdx.x;
    const int warp = tid >> 5, lane = tid & 31;
    const int wm = warp & 3, wn = warp >> 2;
    const int fr = lane >> 2, fq = lane & 3;

    const float* gA = g_etf + (size_t)(by * 128) * D;
    const float* gB = g_etf + (size_t)(bx * 128) * D;

    float acc[2][8][4];
#pragma unroll
    for (int mt = 0; mt < 2; mt++)
#pragma unroll
        for (int nt = 0; nt < 8; nt++)
#pragma unroll
            for (int e = 0; e < 4; e++) acc[mt][nt][e] = 0.0f;

    const int nK = D / BK;

#define LOAD_STAGE(s, k0)                                                      \
    do {                                                                       \
        uint32_t ab = smb + (uint32_t)(s) * (STG_FLT * 4);                     \
        uint32_t bb = ab + 128 * ROWP * 4;                                     \
        _Pragma("unroll")                                                      \
        for (int i = 0; i < 4; i++) {                                          \
            int c = tid + 256 * i;                                             \
            int r = c >> 3;                                                    \
            int kc = (c & 7) << 2;                                             \
            cp_async16(ab + (uint32_t)(r * ROWP + kc) * 4,                     \
                       gA + (size_t)r * D + (k0) + kc);                        \
            cp_async16(bb + (uint32_t)(r * ROWP + kc) * 4,                     \
                       gB + (size_t)r * D + (k0) + kc);                        \
        }                                                                      \
        asm volatile("cp.async.commit_group;" ::: "memory");                   \
    } while (0)

    LOAD_STAGE(0, 0);

    for (int t = 0; t < nK; t++) {
        if (t + 1 < nK) {
            LOAD_STAGE((t + 1) & 1, (t + 1) * BK);
            asm volatile("cp.async.wait_group 1;" ::: "memory");
        } else {
            asm volatile("cp.async.wait_group 0;" ::: "memory");
        }
        __syncthreads();

        const float* As = sm + (t & 1) * STG_FLT;
        const float* Bs = As + 128 * ROWP;

#pragma unroll
        for (int ks = 0; ks < 4; ks++) {
            const int k = ks * 8;
            uint32_t a[2][4], b[8][2];
#pragma unroll
            for (int mt = 0; mt < 2; mt++) {
                const int r0 = wm * 32 + mt * 16 + fr;
                a[mt][0] = __float_as_uint(As[r0 * ROWP + k + fq]);
                a[mt][1] = __float_as_uint(As[(r0 + 8) * ROWP + k + fq]);
                a[mt][2] = __float_as_uint(As[r0 * ROWP + k + fq + 4]);
                a[mt][3] = __float_as_uint(As[(r0 + 8) * ROWP + k + fq + 4]);
            }
#pragma unroll
            for (int nt = 0; nt < 8; nt++) {
                const int c0 = wn * 64 + nt * 8 + fr;
                b[nt][0] = __float_as_uint(Bs[c0 * ROWP + k + fq]);
                b[nt][1] = __float_as_uint(Bs[c0 * ROWP + k + fq + 4]);
            }
#pragma unroll
            for (int mt = 0; mt < 2; mt++)
#pragma unroll
                for (int nt = 0; nt < 8; nt++)
                    mma_tf32_frag(acc[mt][nt], a[mt], b[nt]);
        }
        __syncthreads();
    }

    // ---- stage accumulator tile to smem (reuses pipeline buffers) ----
    float* tile = sm;                      // [128][TS]
#pragma unroll
    for (int mt = 0; mt < 2; mt++) {
#pragma unroll
        for (int nt = 0; nt < 8; nt++) {
            const int r0 = wm * 32 + mt * 16 + fr;
            const int c0 = wn * 64 + nt * 8 + 2 * fq;
            *(float2*)&tile[r0 * TS + c0]       = make_float2(acc[mt][nt][0], acc[mt][nt][1]);
            *(float2*)&tile[(r0 + 8) * TS + c0] = make_float2(acc[mt][nt][2], acc[mt][nt][3]);
        }
    }
    __syncthreads();

    // ---- pass A: per-row stats over this tile's 128 cols ----
    {
        const int r = tid >> 1, h = tid & 1;
        const int gr = by * 128 + r;
        const int cs = g_cs[gr], ce = g_ce[gr];
        const int cbase = bx * 128 + h * 64;
        St st; st.init();
        const float* rowp = &tile[r * TS + h * 64];
#pragma unroll 4
        for (int j4 = 0; j4 < 16; j4++) {
            float4 v = *(const float4*)(rowp + j4 * 4);
            const int jg = cbase + j4 * 4;
            st.upd(v.x, jg + 0, cs, ce);
            st.upd(v.y, jg + 1, cs, ce);
            st.upd(v.z, jg + 2, cs, ce);
            st.upd(v.w, jg + 3, cs, ce);
        }
        st.mergeShfl(1);
        if (h == 0) {
            float* p = &g_part[(size_t)(gr * 32 + bx) * 12];
            ((float4*)p)[0] = make_float4(st.pmin, st.nmax, st.m1, st.s1);
            ((float4*)p)[1] = make_float4(st.m2, st.s2, st.m3, st.s3);
            ((float4*)p)[2] = make_float4(st.m4, st.s4, 0.f, 0.f);
        }
    }

    // ---- pass B (mirror): per-col stats over this tile's 128 rows ----
    if (bx != by) {
        const int c = tid >> 1, h = tid & 1;
        const int gc = bx * 128 + c;
        const int cs = g_cs[gc], ce = g_ce[gc];
        const int rbase = by * 128 + h * 64;
        St st; st.init();
#pragma unroll 4
        for (int r = 0; r < 64; r++) {
            float s = tile[(h * 64 + r) * TS + c];
            st.upd(s, rbase + r, cs, ce);
        }
        st.mergeShfl(1);
        if (h == 0) {
            float* p = &g_part[(size_t)(gc * 32 + by) * 12];
            ((float4*)p)[0] = make_float4(st.pmin, st.nmax, st.m1, st.s1);
            ((float4*)p)[1] = make_float4(st.m2, st.s2, st.m3, st.s3);
            ((float4*)p)[2] = make_float4(st.m4, st.s4, 0.f, 0.f);
        }
    }
}

// ------------------------------- combine ------------------------------------
__global__ __launch_bounds__(256) void combine(int B) {
    const int lane = threadIdx.x & 31;
    const int row = blockIdx.x * 8 + (threadIdx.x >> 5);
    const float* p = &g_part[(size_t)(row * 32 + lane) * 12];
    float4 x0 = ((const float4*)p)[0];
    float4 x1 = ((const float4*)p)[1];
    float4 x2 = ((const float4*)p)[2];
    St st;
    st.pmin = x0.x; st.nmax = x0.y; st.m1 = x0.z; st.s1 = x0.w;
    st.m2 = x1.x; st.s2 = x1.y; st.m3 = x1.z; st.s3 = x1.w;
    st.m4 = x2.x; st.s4 = x2.y;

    st.mergeShfl(16); st.mergeShfl(8); st.mergeShfl(4); st.mergeShfl(2); st.mergeShfl(1);

    if (lane == 0) {
        float se_pos;
        if (st.m1 > NEG_INF)      se_pos = st.m1 + logf(st.s1);
        else if (st.m2 > NEG_INF) se_pos = st.m2 + logf(st.s2);
        else se_pos = -SCALE_C * fmaxf(OPT_P - st.pmin, 0.0f) * (st.pmin - MARGIN_P);
        float se_neg;
        if (st.m3 > NEG_INF)      se_neg = st.m3 + logf(st.s3);
        else if (st.m4 > NEG_INF) se_neg = st.m4 + logf(st.s4);
        else if (st.nmax > NEG_INF)
            se_neg = SCALE_C * fmaxf(st.nmax - OPT_N, 0.0f) * (st.nmax - MARGIN_N);
        else se_neg = 0.0f;

        float z = se_pos + se_neg;
        float pl = (z > 0.0f) ? (z + log1pf(expf(-z))) : log1pf(expf(z));
        float lowf  = (st.pmin > st.nmax) ? 1.0f : 0.0f;
        float medf  = (lowf != 0.0f && st.pmin > MARGIN_P) ? 1.0f : 0.0f;
        float highf = (medf != 0.0f && st.nmax < MARGIN_N) ? 1.0f : 0.0f;

        g_rowout[0 * B + row] = pl;
        g_rowout[1 * B + row] = lowf;
        g_rowout[2 * B + row] = medf;
        g_rowout[3 * B + row] = highf;
    }
}

// ------------------------------ final reduce -------------------------------
__global__ __launch_bounds__(1024) void final_reduce(float* __restrict__ out, int B) {
    __shared__ float4 sh[1024];
    const int tid = threadIdx.x;
    float a0 = 0, a1 = 0, a2 = 0, a3 = 0;
    for (int i = tid; i < B; i += 1024) {
        a0 += g_rowout[i];
        a1 += g_rowout[B + i];
        a2 += g_rowout[2 * B + i];
        a3 += g_rowout[3 * B + i];
    }
    sh[tid] = make_float4(a0, a1, a2, a3);
    __syncthreads();
    for (int off = 512; off > 0; off >>= 1) {
        if (tid < off) {
            float4 a = sh[tid], b = sh[tid + off];
            sh[tid] = make_float4(a.x + b.x, a.y + b.y, a.z + b.z, a.w + b.w);
        }
        __syncthreads();
    }
    if (tid == 0) {
        float inv = 1.0f / (float)B;
        out[0] = sh[0].x * inv;
        out[1] = sh[0].y * inv;
        out[2] = sh[0].z * inv;
        out[3] = sh[0].w * inv;
    }
}

// ------------------------------- launch ------------------------------------
extern "C" void kernel_launch(void* const* d_in, const int* in_sizes, int n_in,
                              void* d_out, int out_size) {
    const float* emb = (const float*)d_in[0];
    const void*  lab = d_in[1];
    const int B = in_sizes[1];
    const int D = in_sizes[0] / B;

    cudaFuncSetAttribute(gemm_fused, cudaFuncAttributeMaxDynamicSharedMemorySize, SMEM_GEMM);
    cudaFuncSetAttribute(sort_labels, cudaFuncAttributeMaxDynamicSharedMemorySize, SORT_SMEM);

    sort_labels<<<1, 256, SORT_SMEM>>>(lab, B);
    to_tf32p<<<B, 128>>>(emb, D);

    dim3 grid(B / 128, B / 128);
    gemm_fused<<<grid, 256, SMEM_GEMM>>>(B, D);

    combine<<<B / 8, 256>>>(B);
    final_reduce<<<1, 1024>>>((float*)d_out, B);
}

// round 5
// speedup vs baseline: 3.0957x; 1.1310x over previous
#include <cuda_runtime.h>
#include <cuda.h>
#include <cuda_bf16.h>
#include <cuda_fp16.h>
#include <math.h>
#include <stdint.h>

// ---------------------------------------------------------------------------
// CircleLoss, fp16-mma fused edition:
//   1) sort_labels : label dtype detect + deterministic stable counting sort
//   2) to_fp16p    : gather-permuted E -> fp16 scratch (same mantissa as tf32)
//   3) gemm_fused  : sim tile via mma.sync m16n8k16 f16 (128x128 CTA tile,
//                    4 warps of 64x64, cp.async 2-stage), tile staged to smem,
//                    row-pass + mirror col-pass -> partial stats. No sim store.
//   4) combine     : one warp per row merges 32 partials -> per-row loss/flags
//   5) final_reduce: deterministic tree reduction -> out[0..3]
// ---------------------------------------------------------------------------

#define MAXB 4096
#define MAXD 512

__device__ __half g_eth[MAXB * MAXD];          // 4 MB permuted fp16 embeddings
__device__ float  g_part[MAXB * 32 * 12];      // 6.3 MB partial states
__device__ float  g_rowout[4 * MAXB];
__device__ int    g_perm[MAXB];
__device__ int    g_cs[MAXB];
__device__ int    g_ce[MAXB];

#define SCALE_C   32.0f
#define MARGIN_P  0.75f
#define MARGIN_N  0.25f
#define OPT_P     1.25f
#define OPT_N     (-0.25f)
#define THETA_C   0.25f
#define NEG_INF   (-INFINITY)

// ------------------------------ helpers ------------------------------------
__device__ __forceinline__ uint32_t smem_u32(const void* p) {
    uint32_t a;
    asm("{ .reg .u64 t; cvta.to.shared.u64 t, %1; cvt.u32.u64 %0, t; }"
        : "=r"(a) : "l"(p));
    return a;
}
__device__ __forceinline__ void cp_async16(uint32_t dst, const void* src) {
    asm volatile("cp.async.cg.shared.global [%0], [%1], 16;" :: "r"(dst), "l"(src));
}
__device__ __forceinline__ void mma_f16_frag(float* d, const uint32_t* a, const uint32_t* b) {
    asm volatile(
        "mma.sync.aligned.m16n8k16.row.col.f32.f16.f16.f32 "
        "{%0,%1,%2,%3}, {%4,%5,%6,%7}, {%8,%9}, {%0,%1,%2,%3};"
        : "+f"(d[0]), "+f"(d[1]), "+f"(d[2]), "+f"(d[3])
        : "r"(a[0]), "r"(a[1]), "r"(a[2]), "r"(a[3]), "r"(b[0]), "r"(b[1]));
}
__device__ __forceinline__ void lse_add(float& m, float& s, float v) {
    if (v > m) { s = s * expf(m - v) + 1.0f; m = v; }
    else       { s += expf(v - m); }
}
__device__ __forceinline__ void lse_merge(float& m1, float& s1, float m2, float s2) {
    if (m2 == NEG_INF) return;
    if (m2 > m1) { s1 = s1 * expf(m1 - m2) + s2; m1 = m2; }
    else         { s1 += s2 * expf(m2 - m1); }
}

struct St {
    float pmin, nmax, m1, s1, m2, s2, m3, s3, m4, s4;
    __device__ __forceinline__ void init() {
        pmin = INFINITY; nmax = NEG_INF;
        m1 = m2 = m3 = m4 = NEG_INF; s1 = s2 = s3 = s4 = 0.f;
    }
    __device__ __forceinline__ void upd(float s, int j, int cs, int ce) {
        if (j >= cs && j < ce) {                       // positive (incl. self)
            pmin = fminf(pmin, s);
            if (s < MARGIN_P) {
                float ip = -SCALE_C * fmaxf(OPT_P - s, 0.0f) * (s - MARGIN_P);
                lse_add(m2, s2, ip);
                if (s + THETA_C < MARGIN_P) lse_add(m1, s1, ip);
            }
        } else {
            nmax = fmaxf(nmax, s);
            if (s > MARGIN_N) {
                float in_ = SCALE_C * fmaxf(s - OPT_N, 0.0f) * (s - MARGIN_N);
                lse_add(m4, s4, in_);
                if (s - THETA_C > MARGIN_N) lse_add(m3, s3, in_);
            }
        }
    }
    __device__ __forceinline__ void mergeShfl(int xorMask) {
        const unsigned FM = 0xffffffffu;
        pmin = fminf(pmin, __shfl_xor_sync(FM, pmin, xorMask));
        nmax = fmaxf(nmax, __shfl_xor_sync(FM, nmax, xorMask));
        float mm, ss;
        mm = __shfl_xor_sync(FM, m1, xorMask); ss = __shfl_xor_sync(FM, s1, xorMask);
        lse_merge(m1, s1, mm, ss);
        mm = __shfl_xor_sync(FM, m2, xorMask); ss = __shfl_xor_sync(FM, s2, xorMask);
        lse_merge(m2, s2, mm, ss);
        mm = __shfl_xor_sync(FM, m3, xorMask); ss = __shfl_xor_sync(FM, s3, xorMask);
        lse_merge(m3, s3, mm, ss);
        mm = __shfl_xor_sync(FM, m4, xorMask); ss = __shfl_xor_sync(FM, s4, xorMask);
        lse_merge(m4, s4, mm, ss);
    }
    __device__ __forceinline__ void store(float* p) const {
        ((float4*)p)[0] = make_float4(pmin, nmax, m1, s1);
        ((float4*)p)[1] = make_float4(m2, s2, m3, s3);
        ((float4*)p)[2] = make_float4(m4, s4, 0.f, 0.f);
    }
};

// ------------------------- deterministic sort -------------------------------
#define NC 128
#define SORT_SMEM (MAXB * 4 + 256 * NC * 2 + (NC + 1) * 4 + 64)

__global__ void sort_labels(const void* __restrict__ lab, int B) {
    extern __shared__ char sms[];
    int* slab = (int*)sms;
    unsigned short* hist = (unsigned short*)(sms + MAXB * 4);
    int* cstart = (int*)(sms + MAXB * 4 + 256 * NC * 2);

    const int t = threadIdx.x;
    const int chk = B / 256;

    __shared__ int is64;
    if (t == 0) {
        const long long* p = (const long long*)lab;
        int ok = 1;
        int n = B < 64 ? B : 64;
        for (int i = 0; i < n; i++) {
            long long v = p[i];
            if (v < 0 || v >= (long long)B) { ok = 0; break; }
        }
        is64 = ok;
    }
    __syncthreads();
    if (is64) {
        const long long* p = (const long long*)lab;
        for (int i = t; i < B; i += 256) slab[i] = (int)p[i];
    } else {
        const int* p = (const int*)lab;
        for (int i = t; i < B; i += 256) slab[i] = p[i];
    }
    for (int i = t; i < 256 * NC; i += 256) hist[i] = 0;
    __syncthreads();

    for (int k = 0; k < chk; k++) hist[t * NC + slab[t * chk + k]]++;
    __syncthreads();

    if (t < NC) {
        int sum = 0;
        for (int ch = 0; ch < 256; ch++) sum += hist[ch * NC + t];
        cstart[t + 1] = sum;
    }
    __syncthreads();
    if (t == 0) {
        cstart[0] = 0;
        for (int c = 1; c <= NC; c++) cstart[c] += cstart[c - 1];
    }
    __syncthreads();
    if (t < NC) {
        int run = cstart[t];
        for (int ch = 0; ch < 256; ch++) {
            int v = hist[ch * NC + t];
            hist[ch * NC + t] = (unsigned short)run;
            run += v;
        }
    }
    __syncthreads();

    for (int k = 0; k < chk; k++) {
        int i = t * chk + k;
        int c = slab[i];
        int p = hist[t * NC + c]++;
        g_perm[p] = i;
    }
    __syncthreads();

    for (int r = t; r < B; r += 256) {
        int c = slab[g_perm[r]];
        g_cs[r] = cstart[c];
        g_ce[r] = cstart[c + 1];
    }
}

// ------------------- permuted fp16 conversion (gather) ----------------------
__global__ __launch_bounds__(128) void to_fp16p(const float* __restrict__ e, int D) {
    const int r = blockIdx.x;
    const int pr = g_perm[r];
    const float4* src = (const float4*)(e + (size_t)pr * D);
    __half2* dst = (__half2*)(g_eth + (size_t)r * D);
    for (int d = threadIdx.x; d < D / 4; d += 128) {
        float4 v = src[d];
        dst[2 * d + 0] = __floats2half2_rn(v.x, v.y);
        dst[2 * d + 1] = __floats2half2_rn(v.z, v.w);
    }
}

// ------------------------ fused GEMM + reduction ----------------------------
// 128x128 CTA tile, 4 warps (2x2) of 64x64 warp tiles, BK=32, fp16 operands.
#define BK 32
#define PH 40                                 // smem pitch in halves (80 B)
#define STAGE_BYTES (2 * 128 * PH * 2)        // A + B per stage = 20480
#define TS 132                                // reduction tile pitch (floats)
#define SMEM_GEMM (128 * TS * 4)              // 67584 >= 2*STAGE_BYTES

__global__ __launch_bounds__(128, 2) void gemm_fused(int B, int D) {
    const int bx = blockIdx.x, by = blockIdx.y;
    if (bx < by) return;

    extern __shared__ float sm[];
    const uint32_t smb = smem_u32(sm);
    const int tid  = threadIdx.x;
    const int warp = tid >> 5, lane = tid & 31;
    const int wm = warp & 1, wn = warp >> 1;       // 2 x 2 warp grid
    const int fr = lane >> 2, fq = lane & 3;

    const __half* gA = g_eth + (size_t)(by * 128) * D;
    const __half* gB = g_eth + (size_t)(bx * 128) * D;

    float acc[4][8][4];
#pragma unroll
    for (int mt = 0; mt < 4; mt++)
#pragma unroll
        for (int nt = 0; nt < 8; nt++)
#pragma unroll
            for (int e = 0; e < 4; e++) acc[mt][nt][e] = 0.0f;

    const int nK = D / BK;                          // 16

    // stage: A 128 rows x 32 halves (4 x 16B per row), same for B
#define LOAD_STAGE(s, k0)                                                      \
    do {                                                                       \
        uint32_t ab = smb + (uint32_t)(s) * STAGE_BYTES;                       \
        uint32_t bb = ab + 128 * PH * 2;                                       \
        _Pragma("unroll")                                                      \
        for (int i = 0; i < 4; i++) {                                          \
            int c = tid + 128 * i;                                             \
            int r = c >> 2;                                                    \
            int kc = (c & 3) << 3;                                             \
            cp_async16(ab + (uint32_t)(r * PH + kc) * 2,                       \
                       gA + (size_t)r * D + (k0) + kc);                        \
            cp_async16(bb + (uint32_t)(r * PH + kc) * 2,                       \
                       gB + (size_t)r * D + (k0) + kc);                        \
        }                                                                      \
        asm volatile("cp.async.commit_group;" ::: "memory");                   \
    } while (0)

    LOAD_STAGE(0, 0);

    for (int t = 0; t < nK; t++) {
        if (t + 1 < nK) {
            LOAD_STAGE((t + 1) & 1, (t + 1) * BK);
            asm volatile("cp.async.wait_group 1;" ::: "memory");
        } else {
            asm volatile("cp.async.wait_group 0;" ::: "memory");
        }
        __syncthreads();

        const __half* As = (const __half*)sm + (size_t)(t & 1) * (STAGE_BYTES / 2);
        const __half* Bs = As + 128 * PH;

#pragma unroll
        for (int ks = 0; ks < 2; ks++) {
            const int k = ks * 16 + 2 * fq;
            uint32_t a[4][4], b[8][2];
#pragma unroll
            for (int mt = 0; mt < 4; mt++) {
                const int r0 = wm * 64 + mt * 16 + fr;
                a[mt][0] = *(const uint32_t*)&As[r0 * PH + k];
                a[mt][1] = *(const uint32_t*)&As[(r0 + 8) * PH + k];
                a[mt][2] = *(const uint32_t*)&As[r0 * PH + k + 8];
                a[mt][3] = *(const uint32_t*)&As[(r0 + 8) * PH + k + 8];
            }
#pragma unroll
            for (int nt = 0; nt < 8; nt++) {
                const int c0 = wn * 64 + nt * 8 + fr;
                b[nt][0] = *(const uint32_t*)&Bs[c0 * PH + k];
                b[nt][1] = *(const uint32_t*)&Bs[c0 * PH + k + 8];
            }
#pragma unroll
            for (int mt = 0; mt < 4; mt++)
#pragma unroll
                for (int nt = 0; nt < 8; nt++)
                    mma_f16_frag(acc[mt][nt], a[mt], b[nt]);
        }
        __syncthreads();
    }

    // ---- stage accumulator tile to smem ----
    float* tile = sm;                               // [128][TS]
#pragma unroll
    for (int mt = 0; mt < 4; mt++) {
#pragma unroll
        for (int nt = 0; nt < 8; nt++) {
            const int r0 = wm * 64 + mt * 16 + fr;
            const int c0 = wn * 64 + nt * 8 + 2 * fq;
            *(float2*)&tile[r0 * TS + c0]       = make_float2(acc[mt][nt][0], acc[mt][nt][1]);
            *(float2*)&tile[(r0 + 8) * TS + c0] = make_float2(acc[mt][nt][2], acc[mt][nt][3]);
        }
    }
    __syncthreads();

    // ---- pass A: per-row stats over this tile's 128 cols (1 thread/row) ----
    {
        const int r = tid;
        const int gr = by * 128 + r;
        const int cs = g_cs[gr], ce = g_ce[gr];
        const int cbase = bx * 128;
        St st; st.init();
        const float* rowp = &tile[r * TS];
#pragma unroll 4
        for (int j4 = 0; j4 < 32; j4++) {
            float4 v = *(const float4*)(rowp + j4 * 4);
            const int jg = cbase + j4 * 4;
            st.upd(v.x, jg + 0, cs, ce);
            st.upd(v.y, jg + 1, cs, ce);
            st.upd(v.z, jg + 2, cs, ce);
            st.upd(v.w, jg + 3, cs, ce);
        }
        st.store(&g_part[(size_t)(gr * 32 + bx) * 12]);
    }

    // ---- pass B (mirror): per-col stats over this tile's 128 rows ----
    if (bx != by) {
        const int c = tid;
        const int gc = bx * 128 + c;
        const int cs = g_cs[gc], ce = g_ce[gc];
        const int rbase = by * 128;
        St st; st.init();
#pragma unroll 4
        for (int r = 0; r < 128; r++)
            st.upd(tile[r * TS + c], rbase + r, cs, ce);
        st.store(&g_part[(size_t)(gc * 32 + by) * 12]);
    }
}

// ------------------------------- combine ------------------------------------
__global__ __launch_bounds__(256) void combine(int B) {
    const int lane = threadIdx.x & 31;
    const int row = blockIdx.x * 8 + (threadIdx.x >> 5);
    const float* p = &g_part[(size_t)(row * 32 + lane) * 12];
    float4 x0 = ((const float4*)p)[0];
    float4 x1 = ((const float4*)p)[1];
    float4 x2 = ((const float4*)p)[2];
    St st;
    st.pmin = x0.x; st.nmax = x0.y; st.m1 = x0.z; st.s1 = x0.w;
    st.m2 = x1.x; st.s2 = x1.y; st.m3 = x1.z; st.s3 = x1.w;
    st.m4 = x2.x; st.s4 = x2.y;

    st.mergeShfl(16); st.mergeShfl(8); st.mergeShfl(4); st.mergeShfl(2); st.mergeShfl(1);

    if (lane == 0) {
        float se_pos;
        if (st.m1 > NEG_INF)      se_pos = st.m1 + logf(st.s1);
        else if (st.m2 > NEG_INF) se_pos = st.m2 + logf(st.s2);
        else se_pos = -SCALE_C * fmaxf(OPT_P - st.pmin, 0.0f) * (st.pmin - MARGIN_P);
        float se_neg;
        if (st.m3 > NEG_INF)      se_neg = st.m3 + logf(st.s3);
        else if (st.m4 > NEG_INF) se_neg = st.m4 + logf(st.s4);
        else if (st.nmax > NEG_INF)
            se_neg = SCALE_C * fmaxf(st.nmax - OPT_N, 0.0f) * (st.nmax - MARGIN_N);
        else se_neg = 0.0f;

        float z = se_pos + se_neg;
        float pl = (z > 0.0f) ? (z + log1pf(expf(-z))) : log1pf(expf(z));
        float lowf  = (st.pmin > st.nmax) ? 1.0f : 0.0f;
        float medf  = (lowf != 0.0f && st.pmin > MARGIN_P) ? 1.0f : 0.0f;
        float highf = (medf != 0.0f && st.nmax < MARGIN_N) ? 1.0f : 0.0f;

        g_rowout[0 * B + row] = pl;
        g_rowout[1 * B + row] = lowf;
        g_rowout[2 * B + row] = medf;
        g_rowout[3 * B + row] = highf;
    }
}

// ------------------------------ final reduce -------------------------------
__global__ __launch_bounds__(1024) void final_reduce(float* __restrict__ out, int B) {
    __shared__ float4 sh[1024];
    const int tid = threadIdx.x;
    float a0 = 0, a1 = 0, a2 = 0, a3 = 0;
    for (int i = tid; i < B; i += 1024) {
        a0 += g_rowout[i];
        a1 += g_rowout[B + i];
        a2 += g_rowout[2 * B + i];
        a3 += g_rowout[3 * B + i];
    }
    sh[tid] = make_float4(a0, a1, a2, a3);
    __syncthreads();
    for (int off = 512; off > 0; off >>= 1) {
        if (tid < off) {
            float4 a = sh[tid], b = sh[tid + off];
            sh[tid] = make_float4(a.x + b.x, a.y + b.y, a.z + b.z, a.w + b.w);
        }
        __syncthreads();
    }
    if (tid == 0) {
        float inv = 1.0f / (float)B;
        out[0] = sh[0].x * inv;
        out[1] = sh[0].y * inv;
        out[2] = sh[0].z * inv;
        out[3] = sh[0].w * inv;
    }
}

// ------------------------------- launch ------------------------------------
extern "C" void kernel_launch(void* const* d_in, const int* in_sizes, int n_in,
                              void* d_out, int out_size) {
    const float* emb = (const float*)d_in[0];
    const void*  lab = d_in[1];
    const int B = in_sizes[1];
    const int D = in_sizes[0] / B;

    cudaFuncSetAttribute(gemm_fused, cudaFuncAttributeMaxDynamicSharedMemorySize, SMEM_GEMM);
    cudaFuncSetAttribute(sort_labels, cudaFuncAttributeMaxDynamicSharedMemorySize, SORT_SMEM);

    sort_labels<<<1, 256, SORT_SMEM>>>(lab, B);
    to_fp16p<<<B, 128>>>(emb, D);

    dim3 grid(B / 128, B / 128);
    gemm_fused<<<grid, 128, SMEM_GEMM>>>(B, D);

    combine<<<B / 8, 256>>>(B);
    final_reduce<<<1, 1024>>>((float*)d_out, B);
}

// round 6
// speedup vs baseline: 3.2928x; 1.0637x over previous
#include <cuda_runtime.h>
#include <cuda.h>
#include <cuda_bf16.h>
#include <cuda_fp16.h>
#include <math.h>
#include <stdint.h>

// ---------------------------------------------------------------------------
// CircleLoss, ldmatrix fp16 edition:
//   1) sort_labels : label dtype detect + deterministic stable counting sort
//   2) to_fp16p    : gather-permuted E -> fp16 scratch
//   3) gemm_fused  : triangular grid (528 CTAs), 128x128 CTA tile, 4 warps of
//                    64x64, BK=64, cp.async 2-stage, ldmatrix.x4 fragment
//                    feeds, fused per-tile row/col reduction. No sim store.
//   4) combine     : one warp per row merges 32 partials -> per-row loss/flags
//   5) final_reduce: deterministic tree reduction -> out[0..3]
// ---------------------------------------------------------------------------

#define MAXB 4096
#define MAXD 512

__device__ __half g_eth[MAXB * MAXD];          // 4 MB permuted fp16 embeddings
__device__ float  g_part[MAXB * 32 * 12];      // 6.3 MB partial states
__device__ float  g_rowout[4 * MAXB];
__device__ int    g_perm[MAXB];
__device__ int    g_cs[MAXB];
__device__ int    g_ce[MAXB];

#define SCALE_C   32.0f
#define MARGIN_P  0.75f
#define MARGIN_N  0.25f
#define OPT_P     1.25f
#define OPT_N     (-0.25f)
#define THETA_C   0.25f
#define NEG_INF   (-INFINITY)

// ------------------------------ helpers ------------------------------------
__device__ __forceinline__ uint32_t smem_u32(const void* p) {
    uint32_t a;
    asm("{ .reg .u64 t; cvta.to.shared.u64 t, %1; cvt.u32.u64 %0, t; }"
        : "=r"(a) : "l"(p));
    return a;
}
__device__ __forceinline__ void cp_async16(uint32_t dst, const void* src) {
    asm volatile("cp.async.cg.shared.global [%0], [%1], 16;" :: "r"(dst), "l"(src));
}
__device__ __forceinline__ void ldm_x4(uint32_t* r, uint32_t addr) {
    asm volatile("ldmatrix.sync.aligned.m8n8.x4.shared.b16 {%0,%1,%2,%3}, [%4];"
        : "=r"(r[0]), "=r"(r[1]), "=r"(r[2]), "=r"(r[3]) : "r"(addr));
}
__device__ __forceinline__ void mma_f16_frag(float* d, const uint32_t* a, const uint32_t* b) {
    asm volatile(
        "mma.sync.aligned.m16n8k16.row.col.f32.f16.f16.f32 "
        "{%0,%1,%2,%3}, {%4,%5,%6,%7}, {%8,%9}, {%0,%1,%2,%3};"
        : "+f"(d[0]), "+f"(d[1]), "+f"(d[2]), "+f"(d[3])
        : "r"(a[0]), "r"(a[1]), "r"(a[2]), "r"(a[3]), "r"(b[0]), "r"(b[1]));
}
__device__ __forceinline__ void lse_add(float& m, float& s, float v) {
    if (v > m) { s = s * expf(m - v) + 1.0f; m = v; }
    else       { s += expf(v - m); }
}
__device__ __forceinline__ void lse_merge(float& m1, float& s1, float m2, float s2) {
    if (m2 == NEG_INF) return;
    if (m2 > m1) { s1 = s1 * expf(m1 - m2) + s2; m1 = m2; }
    else         { s1 += s2 * expf(m2 - m1); }
}

struct St {
    float pmin, nmax, m1, s1, m2, s2, m3, s3, m4, s4;
    __device__ __forceinline__ void init() {
        pmin = INFINITY; nmax = NEG_INF;
        m1 = m2 = m3 = m4 = NEG_INF; s1 = s2 = s3 = s4 = 0.f;
    }
    __device__ __forceinline__ void upd(float s, int j, int cs, int ce) {
        if (j >= cs && j < ce) {                       // positive (incl. self)
            pmin = fminf(pmin, s);
            if (s < MARGIN_P) {
                float ip = -SCALE_C * fmaxf(OPT_P - s, 0.0f) * (s - MARGIN_P);
                lse_add(m2, s2, ip);
                if (s + THETA_C < MARGIN_P) lse_add(m1, s1, ip);
            }
        } else {
            nmax = fmaxf(nmax, s);
            if (s > MARGIN_N) {
                float in_ = SCALE_C * fmaxf(s - OPT_N, 0.0f) * (s - MARGIN_N);
                lse_add(m4, s4, in_);
                if (s - THETA_C > MARGIN_N) lse_add(m3, s3, in_);
            }
        }
    }
    __device__ __forceinline__ void mergeShfl(int xorMask) {
        const unsigned FM = 0xffffffffu;
        pmin = fminf(pmin, __shfl_xor_sync(FM, pmin, xorMask));
        nmax = fmaxf(nmax, __shfl_xor_sync(FM, nmax, xorMask));
        float mm, ss;
        mm = __shfl_xor_sync(FM, m1, xorMask); ss = __shfl_xor_sync(FM, s1, xorMask);
        lse_merge(m1, s1, mm, ss);
        mm = __shfl_xor_sync(FM, m2, xorMask); ss = __shfl_xor_sync(FM, s2, xorMask);
        lse_merge(m2, s2, mm, ss);
        mm = __shfl_xor_sync(FM, m3, xorMask); ss = __shfl_xor_sync(FM, s3, xorMask);
        lse_merge(m3, s3, mm, ss);
        mm = __shfl_xor_sync(FM, m4, xorMask); ss = __shfl_xor_sync(FM, s4, xorMask);
        lse_merge(m4, s4, mm, ss);
    }
    __device__ __forceinline__ void store(float* p) const {
        ((float4*)p)[0] = make_float4(pmin, nmax, m1, s1);
        ((float4*)p)[1] = make_float4(m2, s2, m3, s3);
        ((float4*)p)[2] = make_float4(m4, s4, 0.f, 0.f);
    }
};

// ------------------------- deterministic sort -------------------------------
#define NC 128
#define SORT_SMEM (MAXB * 4 + 256 * NC * 2 + (NC + 1) * 4 + 64)

__global__ void sort_labels(const void* __restrict__ lab, int B) {
    extern __shared__ char sms[];
    int* slab = (int*)sms;
    unsigned short* hist = (unsigned short*)(sms + MAXB * 4);
    int* cstart = (int*)(sms + MAXB * 4 + 256 * NC * 2);

    const int t = threadIdx.x;
    const int chk = B / 256;

    __shared__ int is64;
    if (t == 0) {
        const long long* p = (const long long*)lab;
        int ok = 1;
        int n = B < 64 ? B : 64;
        for (int i = 0; i < n; i++) {
            long long v = p[i];
            if (v < 0 || v >= (long long)B) { ok = 0; break; }
        }
        is64 = ok;
    }
    __syncthreads();
    if (is64) {
        const long long* p = (const long long*)lab;
        for (int i = t; i < B; i += 256) slab[i] = (int)p[i];
    } else {
        const int* p = (const int*)lab;
        for (int i = t; i < B; i += 256) slab[i] = p[i];
    }
    for (int i = t; i < 256 * NC; i += 256) hist[i] = 0;
    __syncthreads();

    for (int k = 0; k < chk; k++) hist[t * NC + slab[t * chk + k]]++;
    __syncthreads();

    if (t < NC) {
        int sum = 0;
        for (int ch = 0; ch < 256; ch++) sum += hist[ch * NC + t];
        cstart[t + 1] = sum;
    }
    __syncthreads();
    if (t == 0) {
        cstart[0] = 0;
        for (int c = 1; c <= NC; c++) cstart[c] += cstart[c - 1];
    }
    __syncthreads();
    if (t < NC) {
        int run = cstart[t];
        for (int ch = 0; ch < 256; ch++) {
            int v = hist[ch * NC + t];
            hist[ch * NC + t] = (unsigned short)run;
            run += v;
        }
    }
    __syncthreads();

    for (int k = 0; k < chk; k++) {
        int i = t * chk + k;
        int c = slab[i];
        int p = hist[t * NC + c]++;
        g_perm[p] = i;
    }
    __syncthreads();

    for (int r = t; r < B; r += 256) {
        int c = slab[g_perm[r]];
        g_cs[r] = cstart[c];
        g_ce[r] = cstart[c + 1];
    }
}

// ------------------- permuted fp16 conversion (gather) ----------------------
__global__ __launch_bounds__(128) void to_fp16p(const float* __restrict__ e, int D) {
    const int r = blockIdx.x;
    const int pr = g_perm[r];
    const float4* src = (const float4*)(e + (size_t)pr * D);
    __half2* dst = (__half2*)(g_eth + (size_t)r * D);
    for (int d = threadIdx.x; d < D / 4; d += 128) {
        float4 v = src[d];
        dst[2 * d + 0] = __floats2half2_rn(v.x, v.y);
        dst[2 * d + 1] = __floats2half2_rn(v.z, v.w);
    }
}

// ------------------------ fused GEMM + reduction ----------------------------
// Triangular grid. 128x128 CTA tile, 4 warps (2x2) of 64x64, BK=64,
// ldmatrix.x4 fragment feeds, fp16 operands, fp32 accum.
#define BK 64
#define PH 72                                  // smem pitch in halves (144 B)
#define STAGE_BYTES (2 * 128 * PH * 2)         // A + B per stage = 36864
#define TS 132                                 // reduction tile pitch (floats)
#define SMEM_GEMM (2 * STAGE_BYTES)            // 73728 >= 128*TS*4 = 67584

__global__ __launch_bounds__(128, 2) void gemm_fused(int B, int D) {
    // linear -> triangular (by <= bx)
    const int t = blockIdx.x;
    int bx = (int)((sqrtf(8.0f * t + 1.0f) - 1.0f) * 0.5f);
    while ((bx + 1) * (bx + 2) / 2 <= t) bx++;
    while (bx * (bx + 1) / 2 > t) bx--;
    const int by = t - bx * (bx + 1) / 2;

    extern __shared__ float sm[];
    const uint32_t smb = smem_u32(sm);
    const int tid  = threadIdx.x;
    const int warp = tid >> 5, lane = tid & 31;
    const int wm = warp & 1, wn = warp >> 1;       // 2 x 2 warp grid
    const int fr = lane >> 2, fq = lane & 3;

    const __half* gA = g_eth + (size_t)(by * 128) * D;
    const __half* gB = g_eth + (size_t)(bx * 128) * D;

    float acc[4][8][4];
#pragma unroll
    for (int mt = 0; mt < 4; mt++)
#pragma unroll
        for (int nt = 0; nt < 8; nt++)
#pragma unroll
            for (int e = 0; e < 4; e++) acc[mt][nt][e] = 0.0f;

    const int nK = D / BK;                          // 8

    // stage: 128 rows x 64 halves per operand, 8 x 16B chunks per row
#define LOAD_STAGE(s, k0)                                                      \
    do {                                                                       \
        uint32_t ab = smb + (uint32_t)(s) * STAGE_BYTES;                       \
        uint32_t bb = ab + 128 * PH * 2;                                       \
        _Pragma("unroll")                                                      \
        for (int i = 0; i < 8; i++) {                                          \
            int c = tid + 128 * i;                                             \
            int r = c >> 3;                                                    \
            int kc = (c & 7) << 3;                                             \
            cp_async16(ab + (uint32_t)(r * PH + kc) * 2,                       \
                       gA + (size_t)r * D + (k0) + kc);                        \
            cp_async16(bb + (uint32_t)(r * PH + kc) * 2,                       \
                       gB + (size_t)r * D + (k0) + kc);                        \
        }                                                                      \
        asm volatile("cp.async.commit_group;" ::: "memory");                   \
    } while (0)

    LOAD_STAGE(0, 0);

    // ldmatrix lane addressing (constant across ks)
    const int a_lr = lane & 15, a_kh = lane >> 4;     // A: row 0-15, k-half
    const int b_gr = lane >> 3, b_rw = lane & 7;      // B: group 0-3, row 0-7

    for (int kt = 0; kt < nK; kt++) {
        if (kt + 1 < nK) {
            LOAD_STAGE((kt + 1) & 1, (kt + 1) * BK);
            asm volatile("cp.async.wait_group 1;" ::: "memory");
        } else {
            asm volatile("cp.async.wait_group 0;" ::: "memory");
        }
        __syncthreads();

        const uint32_t asb = smb + (uint32_t)(kt & 1) * STAGE_BYTES;
        const uint32_t bsb = asb + 128 * PH * 2;

#pragma unroll
        for (int ks = 0; ks < 4; ks++) {
            const int k = ks * 16;
            uint32_t a[4][4], b[8][2];
#pragma unroll
            for (int mt = 0; mt < 4; mt++) {
                const int r = wm * 64 + mt * 16 + a_lr;
                ldm_x4(a[mt], asb + (uint32_t)(r * PH + k + a_kh * 8) * 2);
            }
#pragma unroll
            for (int np = 0; np < 4; np++) {
                const int c = wn * 64 + np * 16 + (b_gr >> 1) * 8 + b_rw;
                uint32_t rr[4];
                ldm_x4(rr, bsb + (uint32_t)(c * PH + k + (b_gr & 1) * 8) * 2);
                b[2 * np][0] = rr[0]; b[2 * np][1] = rr[1];
                b[2 * np + 1][0] = rr[2]; b[2 * np + 1][1] = rr[3];
            }
#pragma unroll
            for (int mt = 0; mt < 4; mt++)
#pragma unroll
                for (int nt = 0; nt < 8; nt++)
                    mma_f16_frag(acc[mt][nt], a[mt], b[nt]);
        }
        __syncthreads();
    }

    // ---- stage accumulator tile to smem ----
    float* tile = sm;                               // [128][TS]
#pragma unroll
    for (int mt = 0; mt < 4; mt++) {
#pragma unroll
        for (int nt = 0; nt < 8; nt++) {
            const int r0 = wm * 64 + mt * 16 + fr;
            const int c0 = wn * 64 + nt * 8 + 2 * fq;
            *(float2*)&tile[r0 * TS + c0]       = make_float2(acc[mt][nt][0], acc[mt][nt][1]);
            *(float2*)&tile[(r0 + 8) * TS + c0] = make_float2(acc[mt][nt][2], acc[mt][nt][3]);
        }
    }
    __syncthreads();

    // ---- pass A: per-row stats over this tile's 128 cols (1 thread/row) ----
    {
        const int r = tid;
        const int gr = by * 128 + r;
        const int cs = g_cs[gr], ce = g_ce[gr];
        const int cbase = bx * 128;
        St st; st.init();
        const float* rowp = &tile[r * TS];
#pragma unroll 4
        for (int j4 = 0; j4 < 32; j4++) {
            float4 v = *(const float4*)(rowp + j4 * 4);
            const int jg = cbase + j4 * 4;
            st.upd(v.x, jg + 0, cs, ce);
            st.upd(v.y, jg + 1, cs, ce);
            st.upd(v.z, jg + 2, cs, ce);
            st.upd(v.w, jg + 3, cs, ce);
        }
        st.store(&g_part[(size_t)(gr * 32 + bx) * 12]);
    }

    // ---- pass B (mirror): per-col stats over this tile's 128 rows ----
    if (bx != by) {
        const int c = tid;
        const int gc = bx * 128 + c;
        const int cs = g_cs[gc], ce = g_ce[gc];
        const int rbase = by * 128;
        St st; st.init();
#pragma unroll 4
        for (int r = 0; r < 128; r++)
            st.upd(tile[r * TS + c], rbase + r, cs, ce);
        st.store(&g_part[(size_t)(gc * 32 + by) * 12]);
    }
}

// ------------------------------- combine ------------------------------------
__global__ __launch_bounds__(256) void combine(int B) {
    const int lane = threadIdx.x & 31;
    const int row = blockIdx.x * 8 + (threadIdx.x >> 5);
    const float* p = &g_part[(size_t)(row * 32 + lane) * 12];
    float4 x0 = ((const float4*)p)[0];
    float4 x1 = ((const float4*)p)[1];
    float4 x2 = ((const float4*)p)[2];
    St st;
    st.pmin = x0.x; st.nmax = x0.y; st.m1 = x0.z; st.s1 = x0.w;
    st.m2 = x1.x; st.s2 = x1.y; st.m3 = x1.z; st.s3 = x1.w;
    st.m4 = x2.x; st.s4 = x2.y;

    st.mergeShfl(16); st.mergeShfl(8); st.mergeShfl(4); st.mergeShfl(2); st.mergeShfl(1);

    if (lane == 0) {
        float se_pos;
        if (st.m1 > NEG_INF)      se_pos = st.m1 + logf(st.s1);
        else if (st.m2 > NEG_INF) se_pos = st.m2 + logf(st.s2);
        else se_pos = -SCALE_C * fmaxf(OPT_P - st.pmin, 0.0f) * (st.pmin - MARGIN_P);
        float se_neg;
        if (st.m3 > NEG_INF)      se_neg = st.m3 + logf(st.s3);
        else if (st.m4 > NEG_INF) se_neg = st.m4 + logf(st.s4);
        else if (st.nmax > NEG_INF)
            se_neg = SCALE_C * fmaxf(st.nmax - OPT_N, 0.0f) * (st.nmax - MARGIN_N);
        else se_neg = 0.0f;

        float z = se_pos + se_neg;
        float pl = (z > 0.0f) ? (z + log1pf(expf(-z))) : log1pf(expf(z));
        float lowf  = (st.pmin > st.nmax) ? 1.0f : 0.0f;
        float medf  = (lowf != 0.0f && st.pmin > MARGIN_P) ? 1.0f : 0.0f;
        float highf = (medf != 0.0f && st.nmax < MARGIN_N) ? 1.0f : 0.0f;

        g_rowout[0 * B + row] = pl;
        g_rowout[1 * B + row] = lowf;
        g_rowout[2 * B + row] = medf;
        g_rowout[3 * B + row] = highf;
    }
}

// ------------------------------ final reduce -------------------------------
__global__ __launch_bounds__(1024) void final_reduce(float* __restrict__ out, int B) {
    __shared__ float4 sh[1024];
    const int tid = threadIdx.x;
    float a0 = 0, a1 = 0, a2 = 0, a3 = 0;
    for (int i = tid; i < B; i += 1024) {
        a0 += g_rowout[i];
        a1 += g_rowout[B + i];
        a2 += g_rowout[2 * B + i];
        a3 += g_rowout[3 * B + i];
    }
    sh[tid] = make_float4(a0, a1, a2, a3);
    __syncthreads();
    for (int off = 512; off > 0; off >>= 1) {
        if (tid < off) {
            float4 a = sh[tid], b = sh[tid + off];
            sh[tid] = make_float4(a.x + b.x, a.y + b.y, a.z + b.z, a.w + b.w);
        }
        __syncthreads();
    }
    if (tid == 0) {
        float inv = 1.0f / (float)B;
        out[0] = sh[0].x * inv;
        out[1] = sh[0].y * inv;
        out[2] = sh[0].z * inv;
        out[3] = sh[0].w * inv;
    }
}

// ------------------------------- launch ------------------------------------
extern "C" void kernel_launch(void* const* d_in, const int* in_sizes, int n_in,
                              void* d_out, int out_size) {
    const float* emb = (const float*)d_in[0];
    const void*  lab = d_in[1];
    const int B = in_sizes[1];
    const int D = in_sizes[0] / B;

    cudaFuncSetAttribute(gemm_fused, cudaFuncAttributeMaxDynamicSharedMemorySize, SMEM_GEMM);
    cudaFuncSetAttribute(sort_labels, cudaFuncAttributeMaxDynamicSharedMemorySize, SORT_SMEM);

    sort_labels<<<1, 256, SORT_SMEM>>>(lab, B);
    to_fp16p<<<B, 128>>>(emb, D);

    const int nb = B / 128;
    const int nT = nb * (nb + 1) / 2;           // 528 triangular blocks
    gemm_fused<<<nT, 128, SMEM_GEMM>>>(B, D);

    combine<<<B / 8, 256>>>(B);
    final_reduce<<<1, 1024>>>((float*)d_out, B);
}

// round 7
// speedup vs baseline: 3.3858x; 1.0282x over previous
#include <cuda_runtime.h>
#include <cuda.h>
#include <cuda_bf16.h>
#include <cuda_fp16.h>
#include <math.h>
#include <stdint.h>

// ---------------------------------------------------------------------------
// CircleLoss, deep-pipeline fp16 edition:
//   1) sort_labels : label dtype detect + deterministic stable counting sort
//   2) to_fp16p    : gather-permuted E -> fp16 scratch
//   3) gemm_fused  : triangular grid (528 CTAs), 128x128 CTA tile, 8 warps of
//                    64x32, BK=64, cp.async 3-stage, ldmatrix.x4 feeds,
//                    concurrent row-pass + mirror col-pass reduction.
//   4) combine     : warp/row merge of 32 partials + per-block float4 sums
//   5) final_reduce: 512-element tree -> out[0..3]
// ---------------------------------------------------------------------------

#define MAXB 4096
#define MAXD 512

__device__ __half g_eth[MAXB * MAXD];          // 4 MB permuted fp16 embeddings
__device__ float  g_part[MAXB * 32 * 12];      // 6.3 MB partial states
__device__ float4 g_bsum[MAXB / 8];            // per-combine-block sums
__device__ int    g_perm[MAXB];
__device__ int    g_cs[MAXB];
__device__ int    g_ce[MAXB];

#define SCALE_C   32.0f
#define MARGIN_P  0.75f
#define MARGIN_N  0.25f
#define OPT_P     1.25f
#define OPT_N     (-0.25f)
#define THETA_C   0.25f
#define NEG_INF   (-INFINITY)

// ------------------------------ helpers ------------------------------------
__device__ __forceinline__ uint32_t smem_u32(const void* p) {
    uint32_t a;
    asm("{ .reg .u64 t; cvta.to.shared.u64 t, %1; cvt.u32.u64 %0, t; }"
        : "=r"(a) : "l"(p));
    return a;
}
__device__ __forceinline__ void cp_async16(uint32_t dst, const void* src) {
    asm volatile("cp.async.cg.shared.global [%0], [%1], 16;" :: "r"(dst), "l"(src));
}
__device__ __forceinline__ void ldm_x4(uint32_t* r, uint32_t addr) {
    asm volatile("ldmatrix.sync.aligned.m8n8.x4.shared.b16 {%0,%1,%2,%3}, [%4];"
        : "=r"(r[0]), "=r"(r[1]), "=r"(r[2]), "=r"(r[3]) : "r"(addr));
}
__device__ __forceinline__ void mma_f16_frag(float* d, const uint32_t* a, const uint32_t* b) {
    asm volatile(
        "mma.sync.aligned.m16n8k16.row.col.f32.f16.f16.f32 "
        "{%0,%1,%2,%3}, {%4,%5,%6,%7}, {%8,%9}, {%0,%1,%2,%3};"
        : "+f"(d[0]), "+f"(d[1]), "+f"(d[2]), "+f"(d[3])
        : "r"(a[0]), "r"(a[1]), "r"(a[2]), "r"(a[3]), "r"(b[0]), "r"(b[1]));
}
__device__ __forceinline__ void lse_add(float& m, float& s, float v) {
    if (v > m) { s = s * expf(m - v) + 1.0f; m = v; }
    else       { s += expf(v - m); }
}
__device__ __forceinline__ void lse_merge(float& m1, float& s1, float m2, float s2) {
    if (m2 == NEG_INF) return;
    if (m2 > m1) { s1 = s1 * expf(m1 - m2) + s2; m1 = m2; }
    else         { s1 += s2 * expf(m2 - m1); }
}

struct St {
    float pmin, nmax, m1, s1, m2, s2, m3, s3, m4, s4;
    __device__ __forceinline__ void init() {
        pmin = INFINITY; nmax = NEG_INF;
        m1 = m2 = m3 = m4 = NEG_INF; s1 = s2 = s3 = s4 = 0.f;
    }
    __device__ __forceinline__ void upd(float s, int j, int cs, int ce) {
        if (j >= cs && j < ce) {                       // positive (incl. self)
            pmin = fminf(pmin, s);
            if (s < MARGIN_P) {
                float ip = -SCALE_C * fmaxf(OPT_P - s, 0.0f) * (s - MARGIN_P);
                lse_add(m2, s2, ip);
                if (s + THETA_C < MARGIN_P) lse_add(m1, s1, ip);
            }
        } else {
            nmax = fmaxf(nmax, s);
            if (s > MARGIN_N) {
                float in_ = SCALE_C * fmaxf(s - OPT_N, 0.0f) * (s - MARGIN_N);
                lse_add(m4, s4, in_);
                if (s - THETA_C > MARGIN_N) lse_add(m3, s3, in_);
            }
        }
    }
    __device__ __forceinline__ void mergeShfl(int xorMask) {
        const unsigned FM = 0xffffffffu;
        pmin = fminf(pmin, __shfl_xor_sync(FM, pmin, xorMask));
        nmax = fmaxf(nmax, __shfl_xor_sync(FM, nmax, xorMask));
        float mm, ss;
        mm = __shfl_xor_sync(FM, m1, xorMask); ss = __shfl_xor_sync(FM, s1, xorMask);
        lse_merge(m1, s1, mm, ss);
        mm = __shfl_xor_sync(FM, m2, xorMask); ss = __shfl_xor_sync(FM, s2, xorMask);
        lse_merge(m2, s2, mm, ss);
        mm = __shfl_xor_sync(FM, m3, xorMask); ss = __shfl_xor_sync(FM, s3, xorMask);
        lse_merge(m3, s3, mm, ss);
        mm = __shfl_xor_sync(FM, m4, xorMask); ss = __shfl_xor_sync(FM, s4, xorMask);
        lse_merge(m4, s4, mm, ss);
    }
    __device__ __forceinline__ void store(float* p) const {
        ((float4*)p)[0] = make_float4(pmin, nmax, m1, s1);
        ((float4*)p)[1] = make_float4(m2, s2, m3, s3);
        ((float4*)p)[2] = make_float4(m4, s4, 0.f, 0.f);
    }
};

// ------------------------- deterministic sort -------------------------------
#define NC 128
#define SORT_SMEM (MAXB * 4 + 256 * NC * 2 + (NC + 1) * 4 + 64)

__global__ void sort_labels(const void* __restrict__ lab, int B) {
    extern __shared__ char sms[];
    int* slab = (int*)sms;
    unsigned short* hist = (unsigned short*)(sms + MAXB * 4);
    int* cstart = (int*)(sms + MAXB * 4 + 256 * NC * 2);

    const int t = threadIdx.x;
    const int chk = B / 256;

    __shared__ int is64;
    if (t == 0) {
        const long long* p = (const long long*)lab;
        int ok = 1;
        int n = B < 64 ? B : 64;
        for (int i = 0; i < n; i++) {
            long long v = p[i];
            if (v < 0 || v >= (long long)B) { ok = 0; break; }
        }
        is64 = ok;
    }
    __syncthreads();
    if (is64) {
        const long long* p = (const long long*)lab;
        for (int i = t; i < B; i += 256) slab[i] = (int)p[i];
    } else {
        const int* p = (const int*)lab;
        for (int i = t; i < B; i += 256) slab[i] = p[i];
    }
    for (int i = t; i < 256 * NC; i += 256) hist[i] = 0;
    __syncthreads();

    for (int k = 0; k < chk; k++) hist[t * NC + slab[t * chk + k]]++;
    __syncthreads();

    if (t < NC) {
        int sum = 0;
        for (int ch = 0; ch < 256; ch++) sum += hist[ch * NC + t];
        cstart[t + 1] = sum;
    }
    __syncthreads();
    if (t == 0) {
        cstart[0] = 0;
        for (int c = 1; c <= NC; c++) cstart[c] += cstart[c - 1];
    }
    __syncthreads();
    if (t < NC) {
        int run = cstart[t];
        for (int ch = 0; ch < 256; ch++) {
            int v = hist[ch * NC + t];
            hist[ch * NC + t] = (unsigned short)run;
            run += v;
        }
    }
    __syncthreads();

    for (int k = 0; k < chk; k++) {
        int i = t * chk + k;
        int c = slab[i];
        int p = hist[t * NC + c]++;
        g_perm[p] = i;
    }
    __syncthreads();

    for (int r = t; r < B; r += 256) {
        int c = slab[g_perm[r]];
        g_cs[r] = cstart[c];
        g_ce[r] = cstart[c + 1];
    }
}

// ------------------- permuted fp16 conversion (gather) ----------------------
__global__ __launch_bounds__(128) void to_fp16p(const float* __restrict__ e, int D) {
    const int r = blockIdx.x;
    const int pr = g_perm[r];
    const float4* src = (const float4*)(e + (size_t)pr * D);
    __half2* dst = (__half2*)(g_eth + (size_t)r * D);
    for (int d = threadIdx.x; d < D / 4; d += 128) {
        float4 v = src[d];
        dst[2 * d + 0] = __floats2half2_rn(v.x, v.y);
        dst[2 * d + 1] = __floats2half2_rn(v.z, v.w);
    }
}

// ------------------------ fused GEMM + reduction ----------------------------
// Triangular grid. 128x128 CTA tile, 8 warps (2m x 4n) of 64x32, BK=64,
// 3-stage cp.async pipeline, ldmatrix.x4 feeds, fp16 operands, fp32 accum.
#define BK 64
#define PH 72                                  // smem pitch in halves (144 B)
#define STAGE_BYTES (2 * 128 * PH * 2)         // A + B per stage = 36864
#define NSTG 3
#define TS 132                                 // reduction tile pitch (floats)
#define SMEM_GEMM (NSTG * STAGE_BYTES)         // 110592 >= 128*TS*4 = 67584

__global__ __launch_bounds__(256, 2) void gemm_fused(int B, int D) {
    // linear -> triangular (by <= bx)
    const int t = blockIdx.x;
    int bx = (int)((sqrtf(8.0f * t + 1.0f) - 1.0f) * 0.5f);
    while ((bx + 1) * (bx + 2) / 2 <= t) bx++;
    while (bx * (bx + 1) / 2 > t) bx--;
    const int by = t - bx * (bx + 1) / 2;

    extern __shared__ float sm[];
    const uint32_t smb = smem_u32(sm);
    const int tid  = threadIdx.x;
    const int warp = tid >> 5, lane = tid & 31;
    const int wm = warp & 1, wn = warp >> 1;       // 2 x 4 warp grid
    const int fr = lane >> 2, fq = lane & 3;

    const __half* gA = g_eth + (size_t)(by * 128) * D;
    const __half* gB = g_eth + (size_t)(bx * 128) * D;

    float acc[4][4][4];
#pragma unroll
    for (int mt = 0; mt < 4; mt++)
#pragma unroll
        for (int nt = 0; nt < 4; nt++)
#pragma unroll
            for (int e = 0; e < 4; e++) acc[mt][nt][e] = 0.0f;

    const int nK = D / BK;                          // 8

    // stage: 128 rows x 64 halves per operand = 1024 x 16B chunks each
#define LOAD_STAGE(s, k0)                                                      \
    do {                                                                       \
        uint32_t ab = smb + (uint32_t)(s) * STAGE_BYTES;                       \
        uint32_t bb = ab + 128 * PH * 2;                                       \
        _Pragma("unroll")                                                      \
        for (int i = 0; i < 4; i++) {                                          \
            int c = tid + 256 * i;                                             \
            int r = c >> 3;                                                    \
            int kc = (c & 7) << 3;                                             \
            cp_async16(ab + (uint32_t)(r * PH + kc) * 2,                       \
                       gA + (size_t)r * D + (k0) + kc);                        \
            cp_async16(bb + (uint32_t)(r * PH + kc) * 2,                       \
                       gB + (size_t)r * D + (k0) + kc);                        \
        }                                                                      \
        asm volatile("cp.async.commit_group;" ::: "memory");                   \
    } while (0)

    LOAD_STAGE(0, 0);
    LOAD_STAGE(1, BK);

    // ldmatrix lane addressing (constant across ks)
    const int a_lr = lane & 15, a_kh = lane >> 4;     // A: row 0-15, k-half
    const int b_gr = lane >> 3, b_rw = lane & 7;      // B: group 0-3, row 0-7

    for (int kt = 0; kt < nK; kt++) {
        if (kt + 2 < nK) {
            LOAD_STAGE((kt + 2) % NSTG, (kt + 2) * BK);
            asm volatile("cp.async.wait_group 2;" ::: "memory");
        } else if (kt + 1 < nK) {
            asm volatile("cp.async.wait_group 1;" ::: "memory");
        } else {
            asm volatile("cp.async.wait_group 0;" ::: "memory");
        }
        __syncthreads();

        const uint32_t asb = smb + (uint32_t)(kt % NSTG) * STAGE_BYTES;
        const uint32_t bsb = asb + 128 * PH * 2;

#pragma unroll
        for (int ks = 0; ks < 4; ks++) {
            const int k = ks * 16;
            uint32_t a[4][4], b[4][2];
#pragma unroll
            for (int mt = 0; mt < 4; mt++) {
                const int r = wm * 64 + mt * 16 + a_lr;
                ldm_x4(a[mt], asb + (uint32_t)(r * PH + k + a_kh * 8) * 2);
            }
#pragma unroll
            for (int np = 0; np < 2; np++) {
                const int c = wn * 32 + np * 16 + (b_gr >> 1) * 8 + b_rw;
                uint32_t rr[4];
                ldm_x4(rr, bsb + (uint32_t)(c * PH + k + (b_gr & 1) * 8) * 2);
                b[2 * np][0] = rr[0]; b[2 * np][1] = rr[1];
                b[2 * np + 1][0] = rr[2]; b[2 * np + 1][1] = rr[3];
            }
#pragma unroll
            for (int mt = 0; mt < 4; mt++)
#pragma unroll
                for (int nt = 0; nt < 4; nt++)
                    mma_f16_frag(acc[mt][nt], a[mt], b[nt]);
        }
        __syncthreads();
    }

    // ---- stage accumulator tile to smem ----
    float* tile = sm;                               // [128][TS]
#pragma unroll
    for (int mt = 0; mt < 4; mt++) {
#pragma unroll
        for (int nt = 0; nt < 4; nt++) {
            const int r0 = wm * 64 + mt * 16 + fr;
            const int c0 = wn * 32 + nt * 8 + 2 * fq;
            *(float2*)&tile[r0 * TS + c0]       = make_float2(acc[mt][nt][0], acc[mt][nt][1]);
            *(float2*)&tile[(r0 + 8) * TS + c0] = make_float2(acc[mt][nt][2], acc[mt][nt][3]);
        }
    }
    __syncthreads();

    // ---- concurrent passes: threads 0-127 rows, 128-255 mirror cols ----
    if (tid < 128) {
        const int r = tid;
        const int gr = by * 128 + r;
        const int cs = g_cs[gr], ce = g_ce[gr];
        const int cbase = bx * 128;
        St st; st.init();
        const float* rowp = &tile[r * TS];
#pragma unroll 4
        for (int j4 = 0; j4 < 32; j4++) {
            float4 v = *(const float4*)(rowp + j4 * 4);
            const int jg = cbase + j4 * 4;
            st.upd(v.x, jg + 0, cs, ce);
            st.upd(v.y, jg + 1, cs, ce);
            st.upd(v.z, jg + 2, cs, ce);
            st.upd(v.w, jg + 3, cs, ce);
        }
        st.store(&g_part[(size_t)(gr * 32 + bx) * 12]);
    } else if (bx != by) {
        const int c = tid - 128;
        const int gc = bx * 128 + c;
        const int cs = g_cs[gc], ce = g_ce[gc];
        const int rbase = by * 128;
        St st; st.init();
#pragma unroll 4
        for (int r = 0; r < 128; r++)
            st.upd(tile[r * TS + c], rbase + r, cs, ce);
        st.store(&g_part[(size_t)(gc * 32 + by) * 12]);
    }
}

// ------------------------------- combine ------------------------------------
// One warp per row merges 32 partials; block accumulates 8 rows -> g_bsum.
__global__ __launch_bounds__(256) void combine(int B) {
    const int lane = threadIdx.x & 31;
    const int w = threadIdx.x >> 5;
    const int row = blockIdx.x * 8 + w;
    const float* p = &g_part[(size_t)(row * 32 + lane) * 12];
    float4 x0 = ((const float4*)p)[0];
    float4 x1 = ((const float4*)p)[1];
    float4 x2 = ((const float4*)p)[2];
    St st;
    st.pmin = x0.x; st.nmax = x0.y; st.m1 = x0.z; st.s1 = x0.w;
    st.m2 = x1.x; st.s2 = x1.y; st.m3 = x1.z; st.s3 = x1.w;
    st.m4 = x2.x; st.s4 = x2.y;

    st.mergeShfl(16); st.mergeShfl(8); st.mergeShfl(4); st.mergeShfl(2); st.mergeShfl(1);

    __shared__ float4 sh[8];
    if (lane == 0) {
        float se_pos;
        if (st.m1 > NEG_INF)      se_pos = st.m1 + logf(st.s1);
        else if (st.m2 > NEG_INF) se_pos = st.m2 + logf(st.s2);
        else se_pos = -SCALE_C * fmaxf(OPT_P - st.pmin, 0.0f) * (st.pmin - MARGIN_P);
        float se_neg;
        if (st.m3 > NEG_INF)      se_neg = st.m3 + logf(st.s3);
        else if (st.m4 > NEG_INF) se_neg = st.m4 + logf(st.s4);
        else if (st.nmax > NEG_INF)
            se_neg = SCALE_C * fmaxf(st.nmax - OPT_N, 0.0f) * (st.nmax - MARGIN_N);
        else se_neg = 0.0f;

        float z = se_pos + se_neg;
        float pl = (z > 0.0f) ? (z + log1pf(expf(-z))) : log1pf(expf(z));
        float lowf  = (st.pmin > st.nmax) ? 1.0f : 0.0f;
        float medf  = (lowf != 0.0f && st.pmin > MARGIN_P) ? 1.0f : 0.0f;
        float highf = (medf != 0.0f && st.nmax < MARGIN_N) ? 1.0f : 0.0f;
        sh[w] = make_float4(pl, lowf, medf, highf);
    }
    __syncthreads();
    if (threadIdx.x == 0) {
        float4 a = sh[0];
#pragma unroll
        for (int i = 1; i < 8; i++) {
            float4 b = sh[i];
            a.x += b.x; a.y += b.y; a.z += b.z; a.w += b.w;
        }
        g_bsum[blockIdx.x] = a;
    }
}

// ------------------------------ final reduce -------------------------------
__global__ __launch_bounds__(512) void final_reduce(float* __restrict__ out, int B) {
    __shared__ float4 sh[512];
    const int tid = threadIdx.x;
    const int nb = B / 8;
    float4 a = (tid < nb) ? g_bsum[tid] : make_float4(0.f, 0.f, 0.f, 0.f);
    sh[tid] = a;
    __syncthreads();
    for (int off = 256; off > 0; off >>= 1) {
        if (tid < off) {
            float4 x = sh[tid], y = sh[tid + off];
            sh[tid] = make_float4(x.x + y.x, x.y + y.y, x.z + y.z, x.w + y.w);
        }
        __syncthreads();
    }
    if (tid == 0) {
        float inv = 1.0f / (float)B;
        out[0] = sh[0].x * inv;
        out[1] = sh[0].y * inv;
        out[2] = sh[0].z * inv;
        out[3] = sh[0].w * inv;
    }
}

// ------------------------------- launch ------------------------------------
extern "C" void kernel_launch(void* const* d_in, const int* in_sizes, int n_in,
                              void* d_out, int out_size) {
    const float* emb = (const float*)d_in[0];
    const void*  lab = d_in[1];
    const int B = in_sizes[1];
    const int D = in_sizes[0] / B;

    cudaFuncSetAttribute(gemm_fused, cudaFuncAttributeMaxDynamicSharedMemorySize, SMEM_GEMM);
    cudaFuncSetAttribute(sort_labels, cudaFuncAttributeMaxDynamicSharedMemorySize, SORT_SMEM);

    sort_labels<<<1, 256, SORT_SMEM>>>(lab, B);
    to_fp16p<<<B, 128>>>(emb, D);

    const int nb = B / 128;
    const int nT = nb * (nb + 1) / 2;           // 528 triangular blocks
    gemm_fused<<<nT, 256, SMEM_GEMM>>>(B, D);

    combine<<<B / 8, 256>>>(B);
    final_reduce<<<1, 512>>>((float*)d_out, B);
}

// round 8
// speedup vs baseline: 3.4454x; 1.0176x over previous
#include <cuda_runtime.h>
#include <cuda.h>
#include <cuda_bf16.h>
#include <cuda_fp16.h>
#include <math.h>
#include <stdint.h>

// ---------------------------------------------------------------------------
// CircleLoss, compressed-partials edition:
//   1) sort_labels : label dtype detect + deterministic stable counting sort
//   2) to_fp16p    : gather-permuted E -> fp16 scratch
//   3) gemm_fused  : triangular grid (528 CTAs), 128x128 CTA tile, 8 warps of
//                    64x32, BK=64, cp.async 3-stage (1 barrier/iter),
//                    ldmatrix.x4 feeds, concurrent row+mirror-col reduction,
//                    partials stored in 8-float L-form (m+log s).
//   4) combine     : warp/row merge of 32 partials; last block (atomic ticket)
//                    reduces block sums -> out[0..3]. No separate reduce.
// ---------------------------------------------------------------------------

#define MAXB 4096
#define MAXD 512

__device__ __half g_eth[MAXB * MAXD];          // 4 MB permuted fp16 embeddings
__device__ float  g_part[MAXB * 32 * 8];       // 4.2 MB partial states (L-form)
__device__ float4 g_bsum[MAXB / 8];            // per-combine-block sums
__device__ int    g_perm[MAXB];
__device__ int    g_cs[MAXB];
__device__ int    g_ce[MAXB];
__device__ int    g_cnt = 0;                   // combine completion ticket

#define SCALE_C   32.0f
#define MARGIN_P  0.75f
#define MARGIN_N  0.25f
#define OPT_P     1.25f
#define OPT_N     (-0.25f)
#define THETA_C   0.25f
#define NEG_INF   (-INFINITY)

// ------------------------------ helpers ------------------------------------
__device__ __forceinline__ uint32_t smem_u32(const void* p) {
    uint32_t a;
    asm("{ .reg .u64 t; cvta.to.shared.u64 t, %1; cvt.u32.u64 %0, t; }"
        : "=r"(a) : "l"(p));
    return a;
}
__device__ __forceinline__ void cp_async16(uint32_t dst, const void* src) {
    asm volatile("cp.async.cg.shared.global [%0], [%1], 16;" :: "r"(dst), "l"(src));
}
__device__ __forceinline__ void ldm_x4(uint32_t* r, uint32_t addr) {
    asm volatile("ldmatrix.sync.aligned.m8n8.x4.shared.b16 {%0,%1,%2,%3}, [%4];"
        : "=r"(r[0]), "=r"(r[1]), "=r"(r[2]), "=r"(r[3]) : "r"(addr));
}
__device__ __forceinline__ void mma_f16_frag(float* d, const uint32_t* a, const uint32_t* b) {
    asm volatile(
        "mma.sync.aligned.m16n8k16.row.col.f32.f16.f16.f32 "
        "{%0,%1,%2,%3}, {%4,%5,%6,%7}, {%8,%9}, {%0,%1,%2,%3};"
        : "+f"(d[0]), "+f"(d[1]), "+f"(d[2]), "+f"(d[3])
        : "r"(a[0]), "r"(a[1]), "r"(a[2]), "r"(a[3]), "r"(b[0]), "r"(b[1]));
}
__device__ __forceinline__ void lse_add(float& m, float& s, float v) {
    if (v > m) { s = s * expf(m - v) + 1.0f; m = v; }
    else       { s += expf(v - m); }
}
__device__ __forceinline__ void lse_merge(float& m1, float& s1, float m2, float s2) {
    if (m2 == NEG_INF) return;
    if (m2 > m1) { s1 = s1 * expf(m1 - m2) + s2; m1 = m2; }
    else         { s1 += s2 * expf(m2 - m1); }
}
__device__ __forceinline__ float lse_close(float m, float s) {
    return (m == NEG_INF) ? NEG_INF : m + logf(s);
}

struct St {
    float pmin, nmax, m1, s1, m2, s2, m3, s3, m4, s4;
    __device__ __forceinline__ void init() {
        pmin = INFINITY; nmax = NEG_INF;
        m1 = m2 = m3 = m4 = NEG_INF; s1 = s2 = s3 = s4 = 0.f;
    }
    __device__ __forceinline__ void upd(float s, int j, int cs, int ce) {
        if (j >= cs && j < ce) {                       // positive (incl. self)
            pmin = fminf(pmin, s);
            if (s < MARGIN_P) {
                float ip = -SCALE_C * fmaxf(OPT_P - s, 0.0f) * (s - MARGIN_P);
                lse_add(m2, s2, ip);
                if (s + THETA_C < MARGIN_P) lse_add(m1, s1, ip);
            }
        } else {
            nmax = fmaxf(nmax, s);
            if (s > MARGIN_N) {
                float in_ = SCALE_C * fmaxf(s - OPT_N, 0.0f) * (s - MARGIN_N);
                lse_add(m4, s4, in_);
                if (s - THETA_C > MARGIN_N) lse_add(m3, s3, in_);
            }
        }
    }
    __device__ __forceinline__ void mergeShfl(int xorMask) {
        const unsigned FM = 0xffffffffu;
        pmin = fminf(pmin, __shfl_xor_sync(FM, pmin, xorMask));
        nmax = fmaxf(nmax, __shfl_xor_sync(FM, nmax, xorMask));
        float mm, ss;
        mm = __shfl_xor_sync(FM, m1, xorMask); ss = __shfl_xor_sync(FM, s1, xorMask);
        lse_merge(m1, s1, mm, ss);
        mm = __shfl_xor_sync(FM, m2, xorMask); ss = __shfl_xor_sync(FM, s2, xorMask);
        lse_merge(m2, s2, mm, ss);
        mm = __shfl_xor_sync(FM, m3, xorMask); ss = __shfl_xor_sync(FM, s3, xorMask);
        lse_merge(m3, s3, mm, ss);
        mm = __shfl_xor_sync(FM, m4, xorMask); ss = __shfl_xor_sync(FM, s4, xorMask);
        lse_merge(m4, s4, mm, ss);
    }
    // L-form store: 8 floats = pmin, nmax, L1..L4, pad, pad
    __device__ __forceinline__ void storeL(float* p) const {
        ((float4*)p)[0] = make_float4(pmin, nmax, lse_close(m1, s1), lse_close(m2, s2));
        ((float4*)p)[1] = make_float4(lse_close(m3, s3), lse_close(m4, s4), 0.f, 0.f);
    }
};

// ------------------------- deterministic sort -------------------------------
#define NC 128
#define SORT_SMEM (MAXB * 4 + 256 * NC * 2 + (NC + 1) * 4 + 64)

__global__ void sort_labels(const void* __restrict__ lab, int B) {
    extern __shared__ char sms[];
    int* slab = (int*)sms;
    unsigned short* hist = (unsigned short*)(sms + MAXB * 4);
    int* cstart = (int*)(sms + MAXB * 4 + 256 * NC * 2);

    const int t = threadIdx.x;
    const int chk = B / 256;

    __shared__ int is64;
    if (t == 0) {
        const long long* p = (const long long*)lab;
        int ok = 1;
        int n = B < 64 ? B : 64;
        for (int i = 0; i < n; i++) {
            long long v = p[i];
            if (v < 0 || v >= (long long)B) { ok = 0; break; }
        }
        is64 = ok;
    }
    __syncthreads();
    if (is64) {
        const long long* p = (const long long*)lab;
        for (int i = t; i < B; i += 256) slab[i] = (int)p[i];
    } else {
        const int* p = (const int*)lab;
        for (int i = t; i < B; i += 256) slab[i] = p[i];
    }
    for (int i = t; i < 256 * NC; i += 256) hist[i] = 0;
    __syncthreads();

    for (int k = 0; k < chk; k++) hist[t * NC + slab[t * chk + k]]++;
    __syncthreads();

    if (t < NC) {
        int sum = 0;
        for (int ch = 0; ch < 256; ch++) sum += hist[ch * NC + t];
        cstart[t + 1] = sum;
    }
    __syncthreads();
    if (t == 0) {
        cstart[0] = 0;
        for (int c = 1; c <= NC; c++) cstart[c] += cstart[c - 1];
    }
    __syncthreads();
    if (t < NC) {
        int run = cstart[t];
        for (int ch = 0; ch < 256; ch++) {
            int v = hist[ch * NC + t];
            hist[ch * NC + t] = (unsigned short)run;
            run += v;
        }
    }
    __syncthreads();

    for (int k = 0; k < chk; k++) {
        int i = t * chk + k;
        int c = slab[i];
        int p = hist[t * NC + c]++;
        g_perm[p] = i;
    }
    __syncthreads();

    for (int r = t; r < B; r += 256) {
        int c = slab[g_perm[r]];
        g_cs[r] = cstart[c];
        g_ce[r] = cstart[c + 1];
    }
}

// ------------------- permuted fp16 conversion (gather) ----------------------
__global__ __launch_bounds__(128) void to_fp16p(const float* __restrict__ e, int D) {
    const int r = blockIdx.x;
    const int pr = g_perm[r];
    const float4* src = (const float4*)(e + (size_t)pr * D);
    __half2* dst = (__half2*)(g_eth + (size_t)r * D);
    for (int d = threadIdx.x; d < D / 4; d += 128) {
        float4 v = src[d];
        dst[2 * d + 0] = __floats2half2_rn(v.x, v.y);
        dst[2 * d + 1] = __floats2half2_rn(v.z, v.w);
    }
}

// ------------------------ fused GEMM + reduction ----------------------------
// Triangular grid. 128x128 CTA tile, 8 warps (2m x 4n) of 64x32, BK=64,
// 3-stage cp.async pipeline (one barrier/iter), ldmatrix.x4 feeds.
#define BK 64
#define PH 72                                  // smem pitch in halves (144 B)
#define STAGE_BYTES (2 * 128 * PH * 2)         // A + B per stage = 36864
#define NSTG 3
#define TS 132                                 // reduction tile pitch (floats)
#define SMEM_GEMM (NSTG * STAGE_BYTES)         // 110592 >= 128*TS*4 = 67584

__global__ __launch_bounds__(256, 2) void gemm_fused(int B, int D) {
    // linear -> triangular (by <= bx)
    const int t = blockIdx.x;
    int bx = (int)((sqrtf(8.0f * t + 1.0f) - 1.0f) * 0.5f);
    while ((bx + 1) * (bx + 2) / 2 <= t) bx++;
    while (bx * (bx + 1) / 2 > t) bx--;
    const int by = t - bx * (bx + 1) / 2;

    extern __shared__ float sm[];
    const uint32_t smb = smem_u32(sm);
    const int tid  = threadIdx.x;
    const int warp = tid >> 5, lane = tid & 31;
    const int wm = warp & 1, wn = warp >> 1;       // 2 x 4 warp grid
    const int fr = lane >> 2, fq = lane & 3;

    const __half* gA = g_eth + (size_t)(by * 128) * D;
    const __half* gB = g_eth + (size_t)(bx * 128) * D;

    float acc[4][4][4];
#pragma unroll
    for (int mt = 0; mt < 4; mt++)
#pragma unroll
        for (int nt = 0; nt < 4; nt++)
#pragma unroll
            for (int e = 0; e < 4; e++) acc[mt][nt][e] = 0.0f;

    const int nK = D / BK;                          // 8

#define LOAD_STAGE(s, k0)                                                      \
    do {                                                                       \
        uint32_t ab = smb + (uint32_t)(s) * STAGE_BYTES;                       \
        uint32_t bb = ab + 128 * PH * 2;                                       \
        _Pragma("unroll")                                                      \
        for (int i = 0; i < 4; i++) {                                          \
            int c = tid + 256 * i;                                             \
            int r = c >> 3;                                                    \
            int kc = (c & 7) << 3;                                             \
            cp_async16(ab + (uint32_t)(r * PH + kc) * 2,                       \
                       gA + (size_t)r * D + (k0) + kc);                        \
            cp_async16(bb + (uint32_t)(r * PH + kc) * 2,                       \
                       gB + (size_t)r * D + (k0) + kc);                        \
        }                                                                      \
        asm volatile("cp.async.commit_group;" ::: "memory");                   \
    } while (0)

    LOAD_STAGE(0, 0);
    LOAD_STAGE(1, BK);

    // ldmatrix lane addressing (constant across ks)
    const int a_lr = lane & 15, a_kh = lane >> 4;     // A: row 0-15, k-half
    const int b_gr = lane >> 3, b_rw = lane & 7;      // B: group 0-3, row 0-7

    for (int kt = 0; kt < nK; kt++) {
        if (kt + 1 < nK) {
            asm volatile("cp.async.wait_group 1;" ::: "memory");
        } else {
            asm volatile("cp.async.wait_group 0;" ::: "memory");
        }
        __syncthreads();
        // Prefetch AFTER the barrier: stage (kt+2)%3 was last read at kt-1,
        // and every warp passed that read before this barrier.
        if (kt + 2 < nK) LOAD_STAGE((kt + 2) % NSTG, (kt + 2) * BK);

        const uint32_t asb = smb + (uint32_t)(kt % NSTG) * STAGE_BYTES;
        const uint32_t bsb = asb + 128 * PH * 2;

#pragma unroll
        for (int ks = 0; ks < 4; ks++) {
            const int k = ks * 16;
            uint32_t a[4][4], b[4][2];
#pragma unroll
            for (int mt = 0; mt < 4; mt++) {
                const int r = wm * 64 + mt * 16 + a_lr;
                ldm_x4(a[mt], asb + (uint32_t)(r * PH + k + a_kh * 8) * 2);
            }
#pragma unroll
            for (int np = 0; np < 2; np++) {
                const int c = wn * 32 + np * 16 + (b_gr >> 1) * 8 + b_rw;
                uint32_t rr[4];
                ldm_x4(rr, bsb + (uint32_t)(c * PH + k + (b_gr & 1) * 8) * 2);
                b[2 * np][0] = rr[0]; b[2 * np][1] = rr[1];
                b[2 * np + 1][0] = rr[2]; b[2 * np + 1][1] = rr[3];
            }
#pragma unroll
            for (int mt = 0; mt < 4; mt++)
#pragma unroll
                for (int nt = 0; nt < 4; nt++)
                    mma_f16_frag(acc[mt][nt], a[mt], b[nt]);
        }
    }
    __syncthreads();   // all mainloop smem reads done before tile staging

    // ---- stage accumulator tile to smem ----
    float* tile = sm;                               // [128][TS]
#pragma unroll
    for (int mt = 0; mt < 4; mt++) {
#pragma unroll
        for (int nt = 0; nt < 4; nt++) {
            const int r0 = wm * 64 + mt * 16 + fr;
            const int c0 = wn * 32 + nt * 8 + 2 * fq;
            *(float2*)&tile[r0 * TS + c0]       = make_float2(acc[mt][nt][0], acc[mt][nt][1]);
            *(float2*)&tile[(r0 + 8) * TS + c0] = make_float2(acc[mt][nt][2], acc[mt][nt][3]);
        }
    }
    __syncthreads();

    // ---- concurrent passes: threads 0-127 rows, 128-255 mirror cols ----
    if (tid < 128) {
        const int r = tid;
        const int gr = by * 128 + r;
        const int cs = g_cs[gr], ce = g_ce[gr];
        const int cbase = bx * 128;
        St st; st.init();
        const float* rowp = &tile[r * TS];
#pragma unroll 4
        for (int j4 = 0; j4 < 32; j4++) {
            float4 v = *(const float4*)(rowp + j4 * 4);
            const int jg = cbase + j4 * 4;
            st.upd(v.x, jg + 0, cs, ce);
            st.upd(v.y, jg + 1, cs, ce);
            st.upd(v.z, jg + 2, cs, ce);
            st.upd(v.w, jg + 3, cs, ce);
        }
        st.storeL(&g_part[(size_t)(gr * 32 + bx) * 8]);
    } else if (bx != by) {
        const int c = tid - 128;
        const int gc = bx * 128 + c;
        const int cs = g_cs[gc], ce = g_ce[gc];
        const int rbase = by * 128;
        St st; st.init();
#pragma unroll 4
        for (int r = 0; r < 128; r++)
            st.upd(tile[r * TS + c], rbase + r, cs, ce);
        st.storeL(&g_part[(size_t)(gc * 32 + by) * 8]);
    }
}

// ------------------------------- combine ------------------------------------
// One warp per row merges 32 L-form partials; block sums 8 rows; the LAST
// block (atomic ticket) tree-reduces all block sums and writes out[0..3].
__global__ __launch_bounds__(256) void combine(float* __restrict__ out, int B) {
    const int lane = threadIdx.x & 31;
    const int w = threadIdx.x >> 5;
    const int row = blockIdx.x * 8 + w;
    const float* p = &g_part[(size_t)(row * 32 + lane) * 8];
    float4 x0 = ((const float4*)p)[0];
    float4 x1 = ((const float4*)p)[1];
    St st;
    st.pmin = x0.x; st.nmax = x0.y;
    st.m1 = x0.z; st.s1 = 1.f;       // L-form: (m=L, s=1); empty -> L=-inf,
    st.m2 = x0.w; st.s2 = 1.f;       // merge treats it as the empty case.
    st.m3 = x1.x; st.s3 = 1.f;
    st.m4 = x1.y; st.s4 = 1.f;

    st.mergeShfl(16); st.mergeShfl(8); st.mergeShfl(4); st.mergeShfl(2); st.mergeShfl(1);

    __shared__ float4 sh[8];
    if (lane == 0) {
        float se_pos;
        if (st.m1 > NEG_INF)      se_pos = st.m1 + logf(st.s1);
        else if (st.m2 > NEG_INF) se_pos = st.m2 + logf(st.s2);
        else se_pos = -SCALE_C * fmaxf(OPT_P - st.pmin, 0.0f) * (st.pmin - MARGIN_P);
        float se_neg;
        if (st.m3 > NEG_INF)      se_neg = st.m3 + logf(st.s3);
        else if (st.m4 > NEG_INF) se_neg = st.m4 + logf(st.s4);
        else if (st.nmax > NEG_INF)
            se_neg = SCALE_C * fmaxf(st.nmax - OPT_N, 0.0f) * (st.nmax - MARGIN_N);
        else se_neg = 0.0f;

        float z = se_pos + se_neg;
        float pl = (z > 0.0f) ? (z + log1pf(expf(-z))) : log1pf(expf(z));
        float lowf  = (st.pmin > st.nmax) ? 1.0f : 0.0f;
        float medf  = (lowf != 0.0f && st.pmin > MARGIN_P) ? 1.0f : 0.0f;
        float highf = (medf != 0.0f && st.nmax < MARGIN_N) ? 1.0f : 0.0f;
        sh[w] = make_float4(pl, lowf, medf, highf);
    }
    __syncthreads();

    __shared__ int sticket;
    if (threadIdx.x == 0) {
        float4 a = sh[0];
#pragma unroll
        for (int i = 1; i < 8; i++) {
            float4 b = sh[i];
            a.x += b.x; a.y += b.y; a.z += b.z; a.w += b.w;
        }
        g_bsum[blockIdx.x] = a;
        __threadfence();
        sticket = atomicAdd(&g_cnt, 1);
    }
    __syncthreads();

    const int nb = B / 8;                      // 512 blocks
    if (sticket == nb - 1) {                   // last block finishes the job
        __shared__ float4 sh4[256];
        const int tid = threadIdx.x;
        float4 a = g_bsum[tid];
        float4 b = g_bsum[tid + 256];
        sh4[tid] = make_float4(a.x + b.x, a.y + b.y, a.z + b.z, a.w + b.w);
        __syncthreads();
        for (int off = 128; off > 0; off >>= 1) {
            if (tid < off) {
                float4 x = sh4[tid], y = sh4[tid + off];
                sh4[tid] = make_float4(x.x + y.x, x.y + y.y, x.z + y.z, x.w + y.w);
            }
            __syncthreads();
        }
        if (tid == 0) {
            float inv = 1.0f / (float)B;
            out[0] = sh4[0].x * inv;
            out[1] = sh4[0].y * inv;
            out[2] = sh4[0].z * inv;
            out[3] = sh4[0].w * inv;
            g_cnt = 0;                         // reset for next graph replay
        }
    }
}

// ------------------------------- launch ------------------------------------
extern "C" void kernel_launch(void* const* d_in, const int* in_sizes, int n_in,
                              void* d_out, int out_size) {
    const float* emb = (const float*)d_in[0];
    const void*  lab = d_in[1];
    const int B = in_sizes[1];
    const int D = in_sizes[0] / B;

    cudaFuncSetAttribute(gemm_fused, cudaFuncAttributeMaxDynamicSharedMemorySize, SMEM_GEMM);
    cudaFuncSetAttribute(sort_labels, cudaFuncAttributeMaxDynamicSharedMemorySize, SORT_SMEM);

    sort_labels<<<1, 256, SORT_SMEM>>>(lab, B);
    to_fp16p<<<B, 128>>>(emb, D);

    const int nb = B / 128;
    const int nT = nb * (nb + 1) / 2;           // 528 triangular blocks
    gemm_fused<<<nT, 256, SMEM_GEMM>>>(B, D);

    combine<<<B / 8, 256>>>((float*)d_out, B);
}